// round 13
// baseline (speedup 1.0000x reference)
#include <cuda_runtime.h>
#include <cuda_bf16.h>
#include <cstdint>

// Problem constants
#define BATCH 32
#define SEQ   256
#define HID   1024
#define HL    512
#define EOUT  256
#define NLANG 5

typedef unsigned long long ull;

// ---------------------------------------------------------------------------
// Scratch (device globals — no allocation allowed)
// ---------------------------------------------------------------------------
__device__ float g_h1[BATCH * SEQ * HID];
__device__ float g_adapted[BATCH * SEQ * HID];
__device__ float g_gates_f[BATCH * SEQ * 4 * HL];
__device__ float g_gates_b[BATCH * SEQ * 4 * HL];
__device__ float g_ys[BATCH * SEQ * 2 * HL];
__device__ float g_h[2][2][HL][BATCH];     // dir, pingpong, UNIT, BATCH
__device__ unsigned g_bar[2];
__device__ int   g_lang[BATCH];
__device__ float2 g_Wt1[NLANG * HID * HID];    // W1^T pre-split (hi,lo)
__device__ float2 g_Wt2[NLANG * HID * HID];    // W2^T pre-split
__device__ float2 g_Wihs_f[4 * HL * HID];      // Wih_f pre-split
__device__ float2 g_Wihs_b[4 * HL * HID];      // Wih_b pre-split

// ---------------------------------------------------------------------------
// tf32 split + mma.sync helpers
// ---------------------------------------------------------------------------
__device__ __forceinline__ void tf32_split(float x, uint32_t& hi, uint32_t& lo)
{
    uint32_t h;
    asm("cvt.rna.tf32.f32 %0, %1;" : "=r"(h) : "f"(x));
    float r = x - __uint_as_float(h);
    uint32_t l;
    asm("cvt.rna.tf32.f32 %0, %1;" : "=r"(l) : "f"(r));
    hi = h; lo = l;
}

__device__ __forceinline__ float2 tf32_split2(float x)
{
    uint32_t h, l;
    tf32_split(x, h, l);
    return make_float2(__uint_as_float(h), __uint_as_float(l));
}

__device__ __forceinline__ void mma8(float* d, const uint32_t* a, const uint32_t* b)
{
    asm volatile(
        "mma.sync.aligned.m16n8k8.row.col.f32.tf32.tf32.f32 "
        "{%0,%1,%2,%3}, {%4,%5,%6,%7}, {%8,%9}, {%0,%1,%2,%3};"
        : "+f"(d[0]), "+f"(d[1]), "+f"(d[2]), "+f"(d[3])
        : "r"(a[0]), "r"(a[1]), "r"(a[2]), "r"(a[3]), "r"(b[0]), "r"(b[1]));
}

__device__ __forceinline__ void ffma2(ull& d, ull a, ull b)
{
    asm("fma.rn.f32x2 %0, %1, %2, %0;" : "+l"(d) : "l"(a), "l"(b));
}

// ---------------------------------------------------------------------------
// 3xtf32 NT GEMM body: C[128,128] = A[128,K] @ B[128,K]^T + bias
// 256 threads, 8 warps (4M x 2N), warp tile 32x64.
// B operand PRE-SPLIT in global (float2 hi/lo). A split on the fly.
// Double-buffered smem, ONE __syncthreads per chunk.
// ---------------------------------------------------------------------------
#define BKC 16
#define MM_PAD2 132
#define SIDX(buf, k, r) ((buf) * (BKC * MM_PAD2) + (k) * MM_PAD2 + (r))
#define MM_SMEM_BYTES (2 * 2 * BKC * MM_PAD2 * 8)   // A+B, 2 buffers, float2

__device__ __forceinline__ void mma_nt_body(
    const float* __restrict__ At, int lda,
    const float2* __restrict__ Bsp, int ldb,   // pre-split B, row-major [128][K]
    const float* __restrict__ bias_t,
    float* __restrict__ Ct, int ldc,
    int K)
{
    extern __shared__ float2 smd[];
    float2* As2 = smd;                      // [2][BKC][MM_PAD2]
    float2* Bs2 = smd + 2 * BKC * MM_PAD2;

    int tid = threadIdx.x;
    int lane = tid & 31, wid = tid >> 5;
    int warpM = wid & 3, warpN = wid >> 2;
    int m0 = warpM * 32, n0w = warpN * 64;
    int g = lane >> 2, t4 = lane & 3;

    int r = tid >> 1, cq = (tid & 1) * 8;
    const float* Arow = At + (size_t)r * lda + cq;
    const float2* Brow = Bsp + (size_t)r * ldb + cq;

    float acc[2][8][4];
#pragma unroll
    for (int mi = 0; mi < 2; mi++)
#pragma unroll
        for (int ni = 0; ni < 8; ni++)
#pragma unroll
            for (int q = 0; q < 4; q++) acc[mi][ni][q] = 0.f;

    float4 pa0, pa1, pb0, pb1, pb2, pb3;
    int nch = K >> 4;

    // load chunk 0
    pa0 = *(const float4*)(Arow);
    pa1 = *(const float4*)(Arow + 4);
    pb0 = *(const float4*)(Brow);
    pb1 = *(const float4*)(Brow + 2);
    pb2 = *(const float4*)(Brow + 4);
    pb3 = *(const float4*)(Brow + 6);
    // store chunk 0 into buffer 0
    {
        As2[SIDX(0, cq + 0, r)] = tf32_split2(pa0.x);
        As2[SIDX(0, cq + 1, r)] = tf32_split2(pa0.y);
        As2[SIDX(0, cq + 2, r)] = tf32_split2(pa0.z);
        As2[SIDX(0, cq + 3, r)] = tf32_split2(pa0.w);
        As2[SIDX(0, cq + 4, r)] = tf32_split2(pa1.x);
        As2[SIDX(0, cq + 5, r)] = tf32_split2(pa1.y);
        As2[SIDX(0, cq + 6, r)] = tf32_split2(pa1.z);
        As2[SIDX(0, cq + 7, r)] = tf32_split2(pa1.w);
        Bs2[SIDX(0, cq + 0, r)] = make_float2(pb0.x, pb0.y);
        Bs2[SIDX(0, cq + 1, r)] = make_float2(pb0.z, pb0.w);
        Bs2[SIDX(0, cq + 2, r)] = make_float2(pb1.x, pb1.y);
        Bs2[SIDX(0, cq + 3, r)] = make_float2(pb1.z, pb1.w);
        Bs2[SIDX(0, cq + 4, r)] = make_float2(pb2.x, pb2.y);
        Bs2[SIDX(0, cq + 5, r)] = make_float2(pb2.z, pb2.w);
        Bs2[SIDX(0, cq + 6, r)] = make_float2(pb3.x, pb3.y);
        Bs2[SIDX(0, cq + 7, r)] = make_float2(pb3.z, pb3.w);
    }
    // load chunk 1 into regs
    if (nch > 1) {
        pa0 = *(const float4*)(Arow + 16);
        pa1 = *(const float4*)(Arow + 16 + 4);
        pb0 = *(const float4*)(Brow + 16);
        pb1 = *(const float4*)(Brow + 16 + 2);
        pb2 = *(const float4*)(Brow + 16 + 4);
        pb3 = *(const float4*)(Brow + 16 + 6);
    }
    __syncthreads();

    for (int c = 0; c < nch; ++c) {
        int buf = c & 1;
        // store chunk c+1 (in regs) into the other buffer
        if (c + 1 < nch) {
            int ob = buf ^ 1;
            As2[SIDX(ob, cq + 0, r)] = tf32_split2(pa0.x);
            As2[SIDX(ob, cq + 1, r)] = tf32_split2(pa0.y);
            As2[SIDX(ob, cq + 2, r)] = tf32_split2(pa0.z);
            As2[SIDX(ob, cq + 3, r)] = tf32_split2(pa0.w);
            As2[SIDX(ob, cq + 4, r)] = tf32_split2(pa1.x);
            As2[SIDX(ob, cq + 5, r)] = tf32_split2(pa1.y);
            As2[SIDX(ob, cq + 6, r)] = tf32_split2(pa1.z);
            As2[SIDX(ob, cq + 7, r)] = tf32_split2(pa1.w);
            Bs2[SIDX(ob, cq + 0, r)] = make_float2(pb0.x, pb0.y);
            Bs2[SIDX(ob, cq + 1, r)] = make_float2(pb0.z, pb0.w);
            Bs2[SIDX(ob, cq + 2, r)] = make_float2(pb1.x, pb1.y);
            Bs2[SIDX(ob, cq + 3, r)] = make_float2(pb1.z, pb1.w);
            Bs2[SIDX(ob, cq + 4, r)] = make_float2(pb2.x, pb2.y);
            Bs2[SIDX(ob, cq + 5, r)] = make_float2(pb2.z, pb2.w);
            Bs2[SIDX(ob, cq + 6, r)] = make_float2(pb3.x, pb3.y);
            Bs2[SIDX(ob, cq + 7, r)] = make_float2(pb3.z, pb3.w);
        }
        // prefetch chunk c+2 into regs (overlaps mma below)
        if (c + 2 < nch) {
            int k0 = (c + 2) * BKC;
            pa0 = *(const float4*)(Arow + k0);
            pa1 = *(const float4*)(Arow + k0 + 4);
            pb0 = *(const float4*)(Brow + k0);
            pb1 = *(const float4*)(Brow + k0 + 2);
            pb2 = *(const float4*)(Brow + k0 + 4);
            pb3 = *(const float4*)(Brow + k0 + 6);
        }
        // mma on buffer buf (chunk c)
#pragma unroll
        for (int ks = 0; ks < BKC; ks += 8) {
            uint32_t ah[2][4], al[2][4];
#pragma unroll
            for (int mi = 0; mi < 2; mi++) {
                int m = m0 + mi * 16;
                float2 a0 = As2[SIDX(buf, ks + t4, m + g)];
                float2 a1 = As2[SIDX(buf, ks + t4, m + g + 8)];
                float2 a2 = As2[SIDX(buf, ks + t4 + 4, m + g)];
                float2 a3 = As2[SIDX(buf, ks + t4 + 4, m + g + 8)];
                ah[mi][0] = __float_as_uint(a0.x); al[mi][0] = __float_as_uint(a0.y);
                ah[mi][1] = __float_as_uint(a1.x); al[mi][1] = __float_as_uint(a1.y);
                ah[mi][2] = __float_as_uint(a2.x); al[mi][2] = __float_as_uint(a2.y);
                ah[mi][3] = __float_as_uint(a3.x); al[mi][3] = __float_as_uint(a3.y);
            }
#pragma unroll
            for (int ni = 0; ni < 8; ni++) {
                int n = n0w + ni * 8 + g;
                float2 b0 = Bs2[SIDX(buf, ks + t4, n)];
                float2 b1 = Bs2[SIDX(buf, ks + t4 + 4, n)];
                uint32_t bh[2], bl[2];
                bh[0] = __float_as_uint(b0.x); bl[0] = __float_as_uint(b0.y);
                bh[1] = __float_as_uint(b1.x); bl[1] = __float_as_uint(b1.y);
#pragma unroll
                for (int mi = 0; mi < 2; mi++) {
                    mma8(acc[mi][ni], ah[mi], bh);
                    mma8(acc[mi][ni], ah[mi], bl);
                    mma8(acc[mi][ni], al[mi], bh);
                }
            }
        }
        __syncthreads();
    }

#pragma unroll
    for (int mi = 0; mi < 2; mi++) {
#pragma unroll
        for (int ni = 0; ni < 8; ni++) {
            int row0 = m0 + mi * 16 + g;
            int col = n0w + ni * 8 + 2 * t4;
            float2 b2 = *(const float2*)&bias_t[col];
            float2 o0 = {acc[mi][ni][0] + b2.x, acc[mi][ni][1] + b2.y};
            float2 o1 = {acc[mi][ni][2] + b2.x, acc[mi][ni][3] + b2.y};
            *(float2*)&Ct[(size_t)row0 * ldc + col] = o0;
            *(float2*)&Ct[(size_t)(row0 + 8) * ldc + col] = o1;
        }
    }
}

__global__ void __launch_bounds__(256, 2) mma_adapter_kernel(
    const float* __restrict__ Abase, const float2* __restrict__ Wt,
    const float* __restrict__ ball, float* __restrict__ Cbase)
{
    int b = blockIdx.z;
    int l = g_lang[b];
    const float* At = Abase + (size_t)b * SEQ * HID + (size_t)blockIdx.y * 128 * HID;
    const float2* Bt = Wt + (size_t)l * HID * HID + (size_t)blockIdx.x * 128 * HID;
    const float* bias_t = ball + (size_t)l * HID + blockIdx.x * 128;
    float* Ct = Cbase + (size_t)b * SEQ * HID + (size_t)blockIdx.y * 128 * HID
              + blockIdx.x * 128;
    mma_nt_body(At, HID, Bt, HID, bias_t, Ct, HID, HID);
}

__global__ void __launch_bounds__(256, 2) mma_nt_kernel(
    const float* __restrict__ A, const float2* __restrict__ B,
    const float* __restrict__ bias, float* __restrict__ C, int K, int ldc)
{
    const float* At = A + (size_t)blockIdx.y * 128 * K;
    const float2* Bt = B + (size_t)blockIdx.x * 128 * K;
    const float* bias_t = bias + blockIdx.x * 128;
    float* Ct = C + (size_t)blockIdx.y * 128 * ldc + blockIdx.x * 128;
    mma_nt_body(At, K, Bt, K, bias_t, Ct, ldc, K);
}

// ---------------------------------------------------------------------------
// W transpose + split: Wt[l][n][k] = split(W[l][k][n])
// ---------------------------------------------------------------------------
__global__ void __launch_bounds__(256) transpose_w_kernel(
    const float* __restrict__ W, float2* __restrict__ Wt)
{
    __shared__ float tile[32][33];
    int l = blockIdx.z;
    int k0 = blockIdx.y * 32, n0 = blockIdx.x * 32;
    const float* Win = W + (size_t)l * HID * HID;
    float2* Wout = Wt + (size_t)l * HID * HID;
    int x = threadIdx.x & 31, y = (threadIdx.x >> 5) * 4;
#pragma unroll
    for (int i = 0; i < 4; i++)
        tile[y + i][x] = Win[(size_t)(k0 + y + i) * HID + n0 + x];
    __syncthreads();
#pragma unroll
    for (int i = 0; i < 4; i++)
        Wout[(size_t)(n0 + y + i) * HID + k0 + x] = tf32_split2(tile[x][y + i]);
}

// Split (no transpose): out[i] = split(in[i])
__global__ void __launch_bounds__(256) split_w_kernel(
    const float* __restrict__ W, float2* __restrict__ Ws, int n)
{
    int i = blockIdx.x * 256 + threadIdx.x;
    if (i < n) Ws[i] = tf32_split2(W[i]);
}

// ---------------------------------------------------------------------------
// Language-id normalization (dtype-robust)
// ---------------------------------------------------------------------------
__global__ void lang_normalize_kernel(const int* __restrict__ raw)
{
    __shared__ int first[32];
    int t = threadIdx.x;
    first[t] = raw[t];
    __syncwarp();
    bool odd_zero = true;
#pragma unroll
    for (int i = 1; i < 32; i += 2) odd_zero &= (first[i] == 0);
    int v = odd_zero ? raw[2 * t] : first[t];
    v = v < 0 ? 0 : (v >= NLANG ? NLANG - 1 : v);
    g_lang[t] = v;
}

// ---------------------------------------------------------------------------
// fp32 SIMT NT GEMM (projection only)
// ---------------------------------------------------------------------------
#define TS_BM 128
#define TS_BN 64
#define TS_BK 16

__global__ void __launch_bounds__(256) nt_gemm_kernel(
    const float* __restrict__ A, const float* __restrict__ Bm,
    const float* __restrict__ bias, float* __restrict__ C,
    int K, int ldc)
{
    __shared__ float As[TS_BK][TS_BM + 4];
    __shared__ float Bs[TS_BK][TS_BN];
    int row0 = blockIdx.y * TS_BM, col0 = blockIdx.x * TS_BN;
    int tid = threadIdx.x;
    int tx = tid & 15, ty = tid >> 4;
    float acc[8][4];
#pragma unroll
    for (int i = 0; i < 8; i++)
#pragma unroll
        for (int j = 0; j < 4; j++) acc[i][j] = 0.f;

    for (int k0 = 0; k0 < K; k0 += TS_BK) {
#pragma unroll
        for (int q = 0; q < 2; ++q) {
            int slot = tid + q * 256;
            int rr = slot >> 2;
            int kk = (slot & 3) * 4;
            float4 v = *(const float4*)&A[(size_t)(row0 + rr) * K + k0 + kk];
            As[kk + 0][rr] = v.x; As[kk + 1][rr] = v.y;
            As[kk + 2][rr] = v.z; As[kk + 3][rr] = v.w;
        }
        {
            int n = tid >> 2;
            int kk4 = (tid & 3) * 4;
            float4 v = *(const float4*)&Bm[(size_t)(col0 + n) * K + k0 + kk4];
            Bs[kk4 + 0][n] = v.x; Bs[kk4 + 1][n] = v.y;
            Bs[kk4 + 2][n] = v.z; Bs[kk4 + 3][n] = v.w;
        }
        __syncthreads();
#pragma unroll
        for (int kk = 0; kk < TS_BK; ++kk) {
            float a[8];
#pragma unroll
            for (int i = 0; i < 8; i++) a[i] = As[kk][ty * 8 + i];
            float4 bv = *(const float4*)&Bs[kk][tx * 4];
#pragma unroll
            for (int i = 0; i < 8; i++) {
                acc[i][0] += a[i] * bv.x; acc[i][1] += a[i] * bv.y;
                acc[i][2] += a[i] * bv.z; acc[i][3] += a[i] * bv.w;
            }
        }
        __syncthreads();
    }
    float4 bb = *(const float4*)&bias[col0 + tx * 4];
#pragma unroll
    for (int i = 0; i < 8; i++) {
        float4 o;
        o.x = acc[i][0] + bb.x; o.y = acc[i][1] + bb.y;
        o.z = acc[i][2] + bb.z; o.w = acc[i][3] + bb.w;
        *(float4*)&C[(size_t)(row0 + ty * 8 + i) * ldc + col0 + tx * 4] = o;
    }
}

// ---------------------------------------------------------------------------
// LayerNorm (biased var) + ReLU, in place
// ---------------------------------------------------------------------------
__global__ void __launch_bounds__(256) ln_relu_kernel(
    float* __restrict__ h, const float* __restrict__ ln_g_all,
    const float* __restrict__ ln_b_all)
{
    int row = blockIdx.x;
    int b = row >> 8;
    int l = g_lang[b];
    float4* x = (float4*)(h + (size_t)row * HID);
    float4 v = x[threadIdx.x];
    float s = v.x + v.y + v.z + v.w;
    float ss = v.x * v.x + v.y * v.y + v.z * v.z + v.w * v.w;
#pragma unroll
    for (int o = 16; o; o >>= 1) {
        s += __shfl_xor_sync(0xffffffffu, s, o);
        ss += __shfl_xor_sync(0xffffffffu, ss, o);
    }
    __shared__ float rs[8], rss[8];
    __shared__ float smean, sinv;
    int w = threadIdx.x >> 5;
    if ((threadIdx.x & 31) == 0) { rs[w] = s; rss[w] = ss; }
    __syncthreads();
    if (threadIdx.x == 0) {
        float S = 0.f, SS = 0.f;
#pragma unroll
        for (int i = 0; i < 8; i++) { S += rs[i]; SS += rss[i]; }
        float mean = S * (1.f / 1024.f);
        float var = SS * (1.f / 1024.f) - mean * mean;
        smean = mean;
        sinv = rsqrtf(var + 1e-5f);
    }
    __syncthreads();
    float mean = smean, inv = sinv;
    float4 g4 = *((const float4*)(ln_g_all + (size_t)l * HID) + threadIdx.x);
    float4 b4 = *((const float4*)(ln_b_all + (size_t)l * HID) + threadIdx.x);
    v.x = fmaxf((v.x - mean) * inv * g4.x + b4.x, 0.f);
    v.y = fmaxf((v.y - mean) * inv * g4.y + b4.y, 0.f);
    v.z = fmaxf((v.z - mean) * inv * g4.z + b4.z, 0.f);
    v.w = fmaxf((v.w - mean) * inv * g4.w + b4.w, 0.f);
    x[threadIdx.x] = v;
}

// ---------------------------------------------------------------------------
// Persistent BiLSTM — register-resident Whh + broadcast h + warp-local staging.
// ---------------------------------------------------------------------------
#define LSTM_HS_FLOATS (512 * 32)                 // 64 KB
#define LSTM_GS_FLOATS (8 * 32 * 36)              // 36 KB
#define LSTM_SMEM_BYTES ((LSTM_HS_FLOATS + LSTM_GS_FLOATS) * 4)

__device__ __forceinline__ float sigf(float x) { return 1.f / (1.f + expf(-x)); }

__global__ void __launch_bounds__(256, 1) lstm_kernel(
    const float* __restrict__ gates_f, const float* __restrict__ gates_b,
    const float* __restrict__ Whh_fw, const float* __restrict__ Whh_bw,
    const int* __restrict__ mask, float* __restrict__ ys)
{
    extern __shared__ float sm[];
    float* hs = sm;                                // [512][32]
    float* gsm = sm + LSTM_HS_FLOATS;              // [8][32][36]

    int tid = threadIdx.x;
    int dir = blockIdx.y;
    int u0 = blockIdx.x * 8;
    const float* Whh = dir ? Whh_bw : Whh_fw;
    const float* G = dir ? gates_b : gates_f;

    int lane = tid & 31, wp = tid >> 5;
    int grow = (lane >> 3) * HL + u0 + (lane & 7);
    int ks = wp * 64;

    float w_reg[64];
    {
        const float4* wsrc = (const float4*)(Whh + (size_t)grow * HL + ks);
#pragma unroll
        for (int j = 0; j < 16; j++) {
            float4 v = wsrc[j];
            w_reg[4 * j + 0] = v.x; w_reg[4 * j + 1] = v.y;
            w_reg[4 * j + 2] = v.z; w_reg[4 * j + 3] = v.w;
        }
    }

    int cu = tid >> 5;
    int cb = tid & 31;
    float c = 0.f;

    float* grow_out = gsm + (wp * 32 + lane) * 36;
    float4* hdst_seg = (float4*)(hs + ks * 32);

    for (int t = 0; t < SEQ; ++t) {
        int s = dir ? (SEQ - 1 - t) : t;
        int pp = t & 1;

        size_t gbase = ((size_t)(cb * SEQ + s)) * (4 * HL) + u0 + cu;
        float gi = G[gbase];
        float gf = G[gbase + 512];
        float gg = G[gbase + 1024];
        float go = G[gbase + 1536];
        int m = mask[cb * SEQ + s];

        {
            const float4* hsrc = (const float4*)(&g_h[dir][pp][0][0]) + ks * 8;
#pragma unroll
            for (int i = 0; i < 16; ++i)
                hdst_seg[lane + 32 * i] = __ldcg(hsrc + lane + 32 * i);
        }
        __syncwarp();

        ull acc[16];
#pragma unroll
        for (int j = 0; j < 16; j++) acc[j] = 0ull;
#pragma unroll
        for (int k = 0; k < 64; ++k) {
            uint32_t wb = __float_as_uint(w_reg[k]);
            ull w2;
            asm("mov.b64 %0, {%1, %1};" : "=l"(w2) : "r"(wb));
            const ulonglong2* hp = (const ulonglong2*)(hs + (ks + k) * 32);
#pragma unroll
            for (int j = 0; j < 8; ++j) {
                ulonglong2 h2 = hp[j];
                ffma2(acc[2 * j], w2, h2.x);
                ffma2(acc[2 * j + 1], w2, h2.y);
            }
        }
#pragma unroll
        for (int j = 0; j < 8; ++j) {
            ulonglong2 o;
            o.x = acc[2 * j]; o.y = acc[2 * j + 1];
            *(ulonglong2*)(grow_out + 4 * j) = o;
        }
        __syncthreads();

        {
            float ii = gi, ff = gf, g2 = gg, oo = go;
#pragma unroll
            for (int w = 0; w < 8; ++w) {
                const float* base = gsm + w * (32 * 36) + cb;
                ii += base[(0 * 8 + cu) * 36];
                ff += base[(1 * 8 + cu) * 36];
                g2 += base[(2 * 8 + cu) * 36];
                oo += base[(3 * 8 + cu) * 36];
            }
            float cn = sigf(ff) * c + sigf(ii) * tanhf(g2);
            float hn = sigf(oo) * tanhf(cn);
            float hold = hs[(u0 + cu) * 32 + cb];
            float hw = m ? hn : hold;
            c = m ? cn : c;
            g_h[dir][1 - pp][u0 + cu][cb] = hw;
            ys[((size_t)(cb * SEQ + s)) * (2 * HL) + dir * HL + u0 + cu] = m ? hn : 0.f;
        }

        __syncthreads();
        if (tid == 0) {
            __threadfence();
            atomicAdd(&g_bar[dir], 1u);
            unsigned tgt = 64u * (unsigned)(t + 1);
            while (*(volatile unsigned*)&g_bar[dir] < tgt) { }
            __threadfence();
        }
        __syncthreads();
    }
}

// ---------------------------------------------------------------------------
// Launch
// ---------------------------------------------------------------------------
extern "C" void kernel_launch(void* const* d_in, const int* in_sizes, int n_in,
                              void* d_out, int out_size)
{
    const float* seq_out = (const float*)d_in[0];
    const int* attn_mask = (const int*)d_in[1];
    const int* lang_raw = (const int*)d_in[2];
    const float* W1 = (const float*)d_in[3];
    const float* b1 = (const float*)d_in[4];
    const float* ln_g = (const float*)d_in[5];
    const float* ln_b = (const float*)d_in[6];
    const float* W2 = (const float*)d_in[7];
    const float* b2 = (const float*)d_in[8];
    const float* Wih_f = (const float*)d_in[9];
    const float* Whh_f = (const float*)d_in[10];
    const float* b_f = (const float*)d_in[11];
    const float* Wih_b = (const float*)d_in[12];
    const float* Whh_b = (const float*)d_in[13];
    const float* b_b = (const float*)d_in[14];
    const float* Wp = (const float*)d_in[15];
    const float* bp = (const float*)d_in[16];
    float* out = (float*)d_out;

    float* h1;       cudaGetSymbolAddress((void**)&h1, g_h1);
    float* adapted;  cudaGetSymbolAddress((void**)&adapted, g_adapted);
    float* gates_f;  cudaGetSymbolAddress((void**)&gates_f, g_gates_f);
    float* gates_b;  cudaGetSymbolAddress((void**)&gates_b, g_gates_b);
    float* ys;       cudaGetSymbolAddress((void**)&ys, g_ys);
    float2* Wt1;     cudaGetSymbolAddress((void**)&Wt1, g_Wt1);
    float2* Wt2;     cudaGetSymbolAddress((void**)&Wt2, g_Wt2);
    float2* Wihs_f;  cudaGetSymbolAddress((void**)&Wihs_f, g_Wihs_f);
    float2* Wihs_b;  cudaGetSymbolAddress((void**)&Wihs_b, g_Wihs_b);
    void* h_ptr;     cudaGetSymbolAddress(&h_ptr, g_h);
    void* bar_ptr;   cudaGetSymbolAddress(&bar_ptr, g_bar);

    cudaFuncSetAttribute(lstm_kernel,
                         cudaFuncAttributeMaxDynamicSharedMemorySize,
                         LSTM_SMEM_BYTES);
    cudaFuncSetAttribute(mma_adapter_kernel,
                         cudaFuncAttributeMaxDynamicSharedMemorySize,
                         MM_SMEM_BYTES);
    cudaFuncSetAttribute(mma_nt_kernel,
                         cudaFuncAttributeMaxDynamicSharedMemorySize,
                         MM_SMEM_BYTES);

    cudaMemsetAsync(h_ptr, 0, sizeof(float) * 2 * 2 * HL * BATCH);
    cudaMemsetAsync(bar_ptr, 0, sizeof(unsigned) * 2);

    // 0) normalize language ids + pre-split weights
    lang_normalize_kernel<<<1, 32>>>(lang_raw);
    transpose_w_kernel<<<dim3(32, 32, NLANG), 256>>>(W1, Wt1);
    transpose_w_kernel<<<dim3(32, 32, NLANG), 256>>>(W2, Wt2);
    split_w_kernel<<<(4 * HL * HID + 255) / 256, 256>>>(Wih_f, Wihs_f, 4 * HL * HID);
    split_w_kernel<<<(4 * HL * HID + 255) / 256, 256>>>(Wih_b, Wihs_b, 4 * HL * HID);
    // 1) adapter GEMM1 (3xtf32 mma.sync, pre-split B, double-buffered)
    mma_adapter_kernel<<<dim3(HID / 128, SEQ / 128, BATCH), 256, MM_SMEM_BYTES>>>(
        seq_out, Wt1, b1, h1);
    // 2) LN + ReLU
    ln_relu_kernel<<<BATCH * SEQ, 256>>>(h1, ln_g, ln_b);
    // 3) adapter GEMM2
    mma_adapter_kernel<<<dim3(HID / 128, SEQ / 128, BATCH), 256, MM_SMEM_BYTES>>>(
        h1, Wt2, b2, adapted);
    // 4) input-gate precompute, both directions
    mma_nt_kernel<<<dim3(4 * HL / 128, BATCH * SEQ / 128), 256, MM_SMEM_BYTES>>>(
        adapted, Wihs_f, b_f, gates_f, HID, 4 * HL);
    mma_nt_kernel<<<dim3(4 * HL / 128, BATCH * SEQ / 128), 256, MM_SMEM_BYTES>>>(
        adapted, Wihs_b, b_b, gates_b, HID, 4 * HL);
    // 5) persistent BiLSTM
    lstm_kernel<<<dim3(64, 2), 256, LSTM_SMEM_BYTES>>>(
        gates_f, gates_b, Whh_f, Whh_b, attn_mask, ys);
    // 6) projection (fp32 SIMT)
    nt_gemm_kernel<<<dim3(EOUT / TS_BN, BATCH * SEQ / TS_BM), 256>>>(
        ys, Wp, bp, out, 2 * HL, EOUT);
}

// round 14
// speedup vs baseline: 1.2535x; 1.2535x over previous
#include <cuda_runtime.h>
#include <cuda_bf16.h>
#include <cstdint>

// Problem constants
#define BATCH 32
#define SEQ   256
#define HID   1024
#define HL    512
#define EOUT  256
#define NLANG 5

typedef unsigned long long ull;

// ---------------------------------------------------------------------------
// Scratch (device globals — no allocation allowed)
// ---------------------------------------------------------------------------
__device__ float g_h1[BATCH * SEQ * HID];
__device__ float g_adapted[BATCH * SEQ * HID];
__device__ float g_gates_f[BATCH * SEQ * 4 * HL];
__device__ float g_gates_b[BATCH * SEQ * 4 * HL];
__device__ float g_ys[BATCH * SEQ * 2 * HL];
__device__ float g_h[2][2][HL][BATCH];     // dir, pingpong, UNIT, BATCH
__device__ unsigned g_bar[2];
__device__ int   g_lang[BATCH];
__device__ float g_Wt1[NLANG * HID * HID];   // W1^T: [l][n][k]
__device__ float g_Wt2[NLANG * HID * HID];   // W2^T

// ---------------------------------------------------------------------------
// tf32 + mma.sync helpers
// ---------------------------------------------------------------------------
__device__ __forceinline__ void tf32_split(float x, uint32_t& hi, uint32_t& lo)
{
    uint32_t h;
    asm("cvt.rna.tf32.f32 %0, %1;" : "=r"(h) : "f"(x));
    float r = x - __uint_as_float(h);
    uint32_t l;
    asm("cvt.rna.tf32.f32 %0, %1;" : "=r"(l) : "f"(r));
    hi = h; lo = l;
}

__device__ __forceinline__ uint32_t tf32_cvt(float x)
{
    uint32_t h;
    asm("cvt.rna.tf32.f32 %0, %1;" : "=r"(h) : "f"(x));
    return h;
}

__device__ __forceinline__ void mma8(float* d, const uint32_t* a, const uint32_t* b)
{
    asm volatile(
        "mma.sync.aligned.m16n8k8.row.col.f32.tf32.tf32.f32 "
        "{%0,%1,%2,%3}, {%4,%5,%6,%7}, {%8,%9}, {%0,%1,%2,%3};"
        : "+f"(d[0]), "+f"(d[1]), "+f"(d[2]), "+f"(d[3])
        : "r"(a[0]), "r"(a[1]), "r"(a[2]), "r"(a[3]), "r"(b[0]), "r"(b[1]));
}

__device__ __forceinline__ void ffma2(ull& d, ull a, ull b)
{
    asm("fma.rn.f32x2 %0, %1, %2, %0;" : "+l"(d) : "l"(a), "l"(b));
}

#define BKC 16
#define MM_PAD2 132
#define MM_PAD1 136

// ---------------------------------------------------------------------------
// 3xtf32 NT GEMM body (adapters): C[128,128] = A @ B^T + bias, ~fp32 accuracy
// (exact R12 configuration: packed float2 hi/lo, two syncs per chunk)
// ---------------------------------------------------------------------------
__device__ __forceinline__ void mma_nt_body_3x(
    const float* __restrict__ At, int lda,
    const float* __restrict__ Bt, int ldb,
    const float* __restrict__ bias_t,
    float* __restrict__ Ct, int ldc,
    int K)
{
    __shared__ float2 As2[BKC][MM_PAD2];
    __shared__ float2 Bs2[BKC][MM_PAD2];

    int tid = threadIdx.x;
    int lane = tid & 31, wid = tid >> 5;
    int warpM = wid & 3, warpN = wid >> 2;
    int m0 = warpM * 32, n0w = warpN * 64;
    int g = lane >> 2, t4 = lane & 3;

    int r = tid >> 1, cq = (tid & 1) * 8;

    float acc[2][8][4];
#pragma unroll
    for (int mi = 0; mi < 2; mi++)
#pragma unroll
        for (int ni = 0; ni < 8; ni++)
#pragma unroll
            for (int q = 0; q < 4; q++) acc[mi][ni][q] = 0.f;

    float4 pa0 = *(const float4*)(At + (size_t)r * lda + cq);
    float4 pa1 = *(const float4*)(At + (size_t)r * lda + cq + 4);
    float4 pb0 = *(const float4*)(Bt + (size_t)r * ldb + cq);
    float4 pb1 = *(const float4*)(Bt + (size_t)r * ldb + cq + 4);

    int nch = K >> 4;
    for (int c = 0; c < nch; ++c) {
        __syncthreads();
        {
            float av[8] = {pa0.x, pa0.y, pa0.z, pa0.w, pa1.x, pa1.y, pa1.z, pa1.w};
            float bv[8] = {pb0.x, pb0.y, pb0.z, pb0.w, pb1.x, pb1.y, pb1.z, pb1.w};
#pragma unroll
            for (int i = 0; i < 8; i++) {
                uint32_t h, l;
                tf32_split(av[i], h, l);
                As2[cq + i][r] = make_float2(__uint_as_float(h), __uint_as_float(l));
                tf32_split(bv[i], h, l);
                Bs2[cq + i][r] = make_float2(__uint_as_float(h), __uint_as_float(l));
            }
        }
        __syncthreads();
        if (c + 1 < nch) {
            int k0 = (c + 1) * BKC;
            pa0 = *(const float4*)(At + (size_t)r * lda + k0 + cq);
            pa1 = *(const float4*)(At + (size_t)r * lda + k0 + cq + 4);
            pb0 = *(const float4*)(Bt + (size_t)r * ldb + k0 + cq);
            pb1 = *(const float4*)(Bt + (size_t)r * ldb + k0 + cq + 4);
        }
#pragma unroll
        for (int ks = 0; ks < BKC; ks += 8) {
            uint32_t ah[2][4], al[2][4];
#pragma unroll
            for (int mi = 0; mi < 2; mi++) {
                int m = m0 + mi * 16;
                float2 a0 = As2[ks + t4][m + g];
                float2 a1 = As2[ks + t4][m + g + 8];
                float2 a2 = As2[ks + t4 + 4][m + g];
                float2 a3 = As2[ks + t4 + 4][m + g + 8];
                ah[mi][0] = __float_as_uint(a0.x); al[mi][0] = __float_as_uint(a0.y);
                ah[mi][1] = __float_as_uint(a1.x); al[mi][1] = __float_as_uint(a1.y);
                ah[mi][2] = __float_as_uint(a2.x); al[mi][2] = __float_as_uint(a2.y);
                ah[mi][3] = __float_as_uint(a3.x); al[mi][3] = __float_as_uint(a3.y);
            }
#pragma unroll
            for (int ni = 0; ni < 8; ni++) {
                int n = n0w + ni * 8 + g;
                float2 b0 = Bs2[ks + t4][n];
                float2 b1 = Bs2[ks + t4 + 4][n];
                uint32_t bh[2], bl[2];
                bh[0] = __float_as_uint(b0.x); bl[0] = __float_as_uint(b0.y);
                bh[1] = __float_as_uint(b1.x); bl[1] = __float_as_uint(b1.y);
#pragma unroll
                for (int mi = 0; mi < 2; mi++) {
                    mma8(acc[mi][ni], ah[mi], bh);
                    mma8(acc[mi][ni], ah[mi], bl);
                    mma8(acc[mi][ni], al[mi], bh);
                }
            }
        }
    }

#pragma unroll
    for (int mi = 0; mi < 2; mi++) {
#pragma unroll
        for (int ni = 0; ni < 8; ni++) {
            int row0 = m0 + mi * 16 + g;
            int col = n0w + ni * 8 + 2 * t4;
            float2 b2 = *(const float2*)&bias_t[col];
            float2 o0 = {acc[mi][ni][0] + b2.x, acc[mi][ni][1] + b2.y};
            float2 o1 = {acc[mi][ni][2] + b2.x, acc[mi][ni][3] + b2.y};
            *(float2*)&Ct[(size_t)row0 * ldc + col] = o0;
            *(float2*)&Ct[(size_t)(row0 + 8) * ldc + col] = o1;
        }
    }
}

// ---------------------------------------------------------------------------
// Single-pass tf32 NT GEMM body (gates): ~2-3e-4 accuracy, 1/3 the mma count.
// ---------------------------------------------------------------------------
__device__ __forceinline__ void mma_nt_body_1x(
    const float* __restrict__ At, int lda,
    const float* __restrict__ Bt, int ldb,
    const float* __restrict__ bias_t,
    float* __restrict__ Ct, int ldc,
    int K)
{
    __shared__ uint32_t As1[BKC][MM_PAD1];
    __shared__ uint32_t Bs1[BKC][MM_PAD1];

    int tid = threadIdx.x;
    int lane = tid & 31, wid = tid >> 5;
    int warpM = wid & 3, warpN = wid >> 2;
    int m0 = warpM * 32, n0w = warpN * 64;
    int g = lane >> 2, t4 = lane & 3;

    int r = tid >> 1, cq = (tid & 1) * 8;

    float acc[2][8][4];
#pragma unroll
    for (int mi = 0; mi < 2; mi++)
#pragma unroll
        for (int ni = 0; ni < 8; ni++)
#pragma unroll
            for (int q = 0; q < 4; q++) acc[mi][ni][q] = 0.f;

    float4 pa0 = *(const float4*)(At + (size_t)r * lda + cq);
    float4 pa1 = *(const float4*)(At + (size_t)r * lda + cq + 4);
    float4 pb0 = *(const float4*)(Bt + (size_t)r * ldb + cq);
    float4 pb1 = *(const float4*)(Bt + (size_t)r * ldb + cq + 4);

    int nch = K >> 4;
    for (int c = 0; c < nch; ++c) {
        __syncthreads();
        {
            float av[8] = {pa0.x, pa0.y, pa0.z, pa0.w, pa1.x, pa1.y, pa1.z, pa1.w};
            float bv[8] = {pb0.x, pb0.y, pb0.z, pb0.w, pb1.x, pb1.y, pb1.z, pb1.w};
#pragma unroll
            for (int i = 0; i < 8; i++) {
                As1[cq + i][r] = tf32_cvt(av[i]);
                Bs1[cq + i][r] = tf32_cvt(bv[i]);
            }
        }
        __syncthreads();
        if (c + 1 < nch) {
            int k0 = (c + 1) * BKC;
            pa0 = *(const float4*)(At + (size_t)r * lda + k0 + cq);
            pa1 = *(const float4*)(At + (size_t)r * lda + k0 + cq + 4);
            pb0 = *(const float4*)(Bt + (size_t)r * ldb + k0 + cq);
            pb1 = *(const float4*)(Bt + (size_t)r * ldb + k0 + cq + 4);
        }
#pragma unroll
        for (int ks = 0; ks < BKC; ks += 8) {
            uint32_t ah[2][4];
#pragma unroll
            for (int mi = 0; mi < 2; mi++) {
                int m = m0 + mi * 16;
                ah[mi][0] = As1[ks + t4][m + g];
                ah[mi][1] = As1[ks + t4][m + g + 8];
                ah[mi][2] = As1[ks + t4 + 4][m + g];
                ah[mi][3] = As1[ks + t4 + 4][m + g + 8];
            }
#pragma unroll
            for (int ni = 0; ni < 8; ni++) {
                int n = n0w + ni * 8 + g;
                uint32_t bh[2];
                bh[0] = Bs1[ks + t4][n];
                bh[1] = Bs1[ks + t4 + 4][n];
                mma8(acc[0][ni], ah[0], bh);
                mma8(acc[1][ni], ah[1], bh);
            }
        }
    }

#pragma unroll
    for (int mi = 0; mi < 2; mi++) {
#pragma unroll
        for (int ni = 0; ni < 8; ni++) {
            int row0 = m0 + mi * 16 + g;
            int col = n0w + ni * 8 + 2 * t4;
            float2 b2 = *(const float2*)&bias_t[col];
            float2 o0 = {acc[mi][ni][0] + b2.x, acc[mi][ni][1] + b2.y};
            float2 o1 = {acc[mi][ni][2] + b2.x, acc[mi][ni][3] + b2.y};
            *(float2*)&Ct[(size_t)row0 * ldc + col] = o0;
            *(float2*)&Ct[(size_t)(row0 + 8) * ldc + col] = o1;
        }
    }
}

__global__ void __launch_bounds__(256, 2) mma_adapter_kernel(
    const float* __restrict__ Abase, const float* __restrict__ Wt,
    const float* __restrict__ ball, float* __restrict__ Cbase)
{
    int b = blockIdx.z;
    int l = g_lang[b];
    const float* At = Abase + (size_t)b * SEQ * HID + (size_t)blockIdx.y * 128 * HID;
    const float* Bt = Wt + (size_t)l * HID * HID + (size_t)blockIdx.x * 128 * HID;
    const float* bias_t = ball + (size_t)l * HID + blockIdx.x * 128;
    float* Ct = Cbase + (size_t)b * SEQ * HID + (size_t)blockIdx.y * 128 * HID
              + blockIdx.x * 128;
    mma_nt_body_3x(At, HID, Bt, HID, bias_t, Ct, HID, HID);
}

__global__ void __launch_bounds__(256, 2) mma_nt1x_kernel(
    const float* __restrict__ A, const float* __restrict__ B,
    const float* __restrict__ bias, float* __restrict__ C, int K, int ldc)
{
    const float* At = A + (size_t)blockIdx.y * 128 * K;
    const float* Bt = B + (size_t)blockIdx.x * 128 * K;
    const float* bias_t = bias + blockIdx.x * 128;
    float* Ct = C + (size_t)blockIdx.y * 128 * ldc + blockIdx.x * 128;
    mma_nt_body_1x(At, K, Bt, K, bias_t, Ct, ldc, K);
}

// ---------------------------------------------------------------------------
// W transpose: Wt[l][n][k] = W[l][k][n]
// ---------------------------------------------------------------------------
__global__ void __launch_bounds__(256) transpose_w_kernel(
    const float* __restrict__ W, float* __restrict__ Wt)
{
    __shared__ float tile[32][33];
    int l = blockIdx.z;
    int k0 = blockIdx.y * 32, n0 = blockIdx.x * 32;
    const float* Win = W + (size_t)l * HID * HID;
    float* Wout = Wt + (size_t)l * HID * HID;
    int x = threadIdx.x & 31, y = (threadIdx.x >> 5) * 4;
#pragma unroll
    for (int i = 0; i < 4; i++)
        tile[y + i][x] = Win[(size_t)(k0 + y + i) * HID + n0 + x];
    __syncthreads();
#pragma unroll
    for (int i = 0; i < 4; i++)
        Wout[(size_t)(n0 + y + i) * HID + k0 + x] = tile[x][y + i];
}

// ---------------------------------------------------------------------------
// Language-id normalization (dtype-robust)
// ---------------------------------------------------------------------------
__global__ void lang_normalize_kernel(const int* __restrict__ raw)
{
    __shared__ int first[32];
    int t = threadIdx.x;
    first[t] = raw[t];
    __syncwarp();
    bool odd_zero = true;
#pragma unroll
    for (int i = 1; i < 32; i += 2) odd_zero &= (first[i] == 0);
    int v = odd_zero ? raw[2 * t] : first[t];
    v = v < 0 ? 0 : (v >= NLANG ? NLANG - 1 : v);
    g_lang[t] = v;
}

// ---------------------------------------------------------------------------
// fp32 SIMT NT GEMM (projection only)
// ---------------------------------------------------------------------------
#define TS_BM 128
#define TS_BN 64
#define TS_BK 16

__global__ void __launch_bounds__(256) nt_gemm_kernel(
    const float* __restrict__ A, const float* __restrict__ Bm,
    const float* __restrict__ bias, float* __restrict__ C,
    int K, int ldc)
{
    __shared__ float As[TS_BK][TS_BM + 4];
    __shared__ float Bs[TS_BK][TS_BN];
    int row0 = blockIdx.y * TS_BM, col0 = blockIdx.x * TS_BN;
    int tid = threadIdx.x;
    int tx = tid & 15, ty = tid >> 4;
    float acc[8][4];
#pragma unroll
    for (int i = 0; i < 8; i++)
#pragma unroll
        for (int j = 0; j < 4; j++) acc[i][j] = 0.f;

    for (int k0 = 0; k0 < K; k0 += TS_BK) {
#pragma unroll
        for (int q = 0; q < 2; ++q) {
            int slot = tid + q * 256;
            int rr = slot >> 2;
            int kk = (slot & 3) * 4;
            float4 v = *(const float4*)&A[(size_t)(row0 + rr) * K + k0 + kk];
            As[kk + 0][rr] = v.x; As[kk + 1][rr] = v.y;
            As[kk + 2][rr] = v.z; As[kk + 3][rr] = v.w;
        }
        {
            int n = tid >> 2;
            int kk4 = (tid & 3) * 4;
            float4 v = *(const float4*)&Bm[(size_t)(col0 + n) * K + k0 + kk4];
            Bs[kk4 + 0][n] = v.x; Bs[kk4 + 1][n] = v.y;
            Bs[kk4 + 2][n] = v.z; Bs[kk4 + 3][n] = v.w;
        }
        __syncthreads();
#pragma unroll
        for (int kk = 0; kk < TS_BK; ++kk) {
            float a[8];
#pragma unroll
            for (int i = 0; i < 8; i++) a[i] = As[kk][ty * 8 + i];
            float4 bv = *(const float4*)&Bs[kk][tx * 4];
#pragma unroll
            for (int i = 0; i < 8; i++) {
                acc[i][0] += a[i] * bv.x; acc[i][1] += a[i] * bv.y;
                acc[i][2] += a[i] * bv.z; acc[i][3] += a[i] * bv.w;
            }
        }
        __syncthreads();
    }
    float4 bb = *(const float4*)&bias[col0 + tx * 4];
#pragma unroll
    for (int i = 0; i < 8; i++) {
        float4 o;
        o.x = acc[i][0] + bb.x; o.y = acc[i][1] + bb.y;
        o.z = acc[i][2] + bb.z; o.w = acc[i][3] + bb.w;
        *(float4*)&C[(size_t)(row0 + ty * 8 + i) * ldc + col0 + tx * 4] = o;
    }
}

// ---------------------------------------------------------------------------
// LayerNorm (biased var) + ReLU, in place
// ---------------------------------------------------------------------------
__global__ void __launch_bounds__(256) ln_relu_kernel(
    float* __restrict__ h, const float* __restrict__ ln_g_all,
    const float* __restrict__ ln_b_all)
{
    int row = blockIdx.x;
    int b = row >> 8;
    int l = g_lang[b];
    float4* x = (float4*)(h + (size_t)row * HID);
    float4 v = x[threadIdx.x];
    float s = v.x + v.y + v.z + v.w;
    float ss = v.x * v.x + v.y * v.y + v.z * v.z + v.w * v.w;
#pragma unroll
    for (int o = 16; o; o >>= 1) {
        s += __shfl_xor_sync(0xffffffffu, s, o);
        ss += __shfl_xor_sync(0xffffffffu, ss, o);
    }
    __shared__ float rs[8], rss[8];
    __shared__ float smean, sinv;
    int w = threadIdx.x >> 5;
    if ((threadIdx.x & 31) == 0) { rs[w] = s; rss[w] = ss; }
    __syncthreads();
    if (threadIdx.x == 0) {
        float S = 0.f, SS = 0.f;
#pragma unroll
        for (int i = 0; i < 8; i++) { S += rs[i]; SS += rss[i]; }
        float mean = S * (1.f / 1024.f);
        float var = SS * (1.f / 1024.f) - mean * mean;
        smean = mean;
        sinv = rsqrtf(var + 1e-5f);
    }
    __syncthreads();
    float mean = smean, inv = sinv;
    float4 g4 = *((const float4*)(ln_g_all + (size_t)l * HID) + threadIdx.x);
    float4 b4 = *((const float4*)(ln_b_all + (size_t)l * HID) + threadIdx.x);
    v.x = fmaxf((v.x - mean) * inv * g4.x + b4.x, 0.f);
    v.y = fmaxf((v.y - mean) * inv * g4.y + b4.y, 0.f);
    v.z = fmaxf((v.z - mean) * inv * g4.z + b4.z, 0.f);
    v.w = fmaxf((v.w - mean) * inv * g4.w + b4.w, 0.f);
    x[threadIdx.x] = v;
}

// ---------------------------------------------------------------------------
// Persistent BiLSTM — register-resident Whh + broadcast h + warp-local staging.
// ---------------------------------------------------------------------------
#define LSTM_HS_FLOATS (512 * 32)                 // 64 KB
#define LSTM_GS_FLOATS (8 * 32 * 36)              // 36 KB
#define LSTM_SMEM_BYTES ((LSTM_HS_FLOATS + LSTM_GS_FLOATS) * 4)

__device__ __forceinline__ float sigf(float x) { return 1.f / (1.f + expf(-x)); }

__global__ void __launch_bounds__(256, 1) lstm_kernel(
    const float* __restrict__ gates_f, const float* __restrict__ gates_b,
    const float* __restrict__ Whh_fw, const float* __restrict__ Whh_bw,
    const int* __restrict__ mask, float* __restrict__ ys)
{
    extern __shared__ float sm[];
    float* hs = sm;                                // [512][32]
    float* gsm = sm + LSTM_HS_FLOATS;              // [8][32][36]

    int tid = threadIdx.x;
    int dir = blockIdx.y;
    int u0 = blockIdx.x * 8;
    const float* Whh = dir ? Whh_bw : Whh_fw;
    const float* G = dir ? gates_b : gates_f;

    int lane = tid & 31, wp = tid >> 5;
    int grow = (lane >> 3) * HL + u0 + (lane & 7);
    int ks = wp * 64;

    float w_reg[64];
    {
        const float4* wsrc = (const float4*)(Whh + (size_t)grow * HL + ks);
#pragma unroll
        for (int j = 0; j < 16; j++) {
            float4 v = wsrc[j];
            w_reg[4 * j + 0] = v.x; w_reg[4 * j + 1] = v.y;
            w_reg[4 * j + 2] = v.z; w_reg[4 * j + 3] = v.w;
        }
    }

    int cu = tid >> 5;
    int cb = tid & 31;
    float c = 0.f;

    float* grow_out = gsm + (wp * 32 + lane) * 36;
    float4* hdst_seg = (float4*)(hs + ks * 32);

    for (int t = 0; t < SEQ; ++t) {
        int s = dir ? (SEQ - 1 - t) : t;
        int pp = t & 1;

        size_t gbase = ((size_t)(cb * SEQ + s)) * (4 * HL) + u0 + cu;
        float gi = G[gbase];
        float gf = G[gbase + 512];
        float gg = G[gbase + 1024];
        float go = G[gbase + 1536];
        int m = mask[cb * SEQ + s];

        {
            const float4* hsrc = (const float4*)(&g_h[dir][pp][0][0]) + ks * 8;
#pragma unroll
            for (int i = 0; i < 16; ++i)
                hdst_seg[lane + 32 * i] = __ldcg(hsrc + lane + 32 * i);
        }
        __syncwarp();

        ull acc[16];
#pragma unroll
        for (int j = 0; j < 16; j++) acc[j] = 0ull;
#pragma unroll
        for (int k = 0; k < 64; ++k) {
            uint32_t wb = __float_as_uint(w_reg[k]);
            ull w2;
            asm("mov.b64 %0, {%1, %1};" : "=l"(w2) : "r"(wb));
            const ulonglong2* hp = (const ulonglong2*)(hs + (ks + k) * 32);
#pragma unroll
            for (int j = 0; j < 8; ++j) {
                ulonglong2 h2 = hp[j];
                ffma2(acc[2 * j], w2, h2.x);
                ffma2(acc[2 * j + 1], w2, h2.y);
            }
        }
#pragma unroll
        for (int j = 0; j < 8; ++j) {
            ulonglong2 o;
            o.x = acc[2 * j]; o.y = acc[2 * j + 1];
            *(ulonglong2*)(grow_out + 4 * j) = o;
        }
        __syncthreads();

        {
            float ii = gi, ff = gf, g2 = gg, oo = go;
#pragma unroll
            for (int w = 0; w < 8; ++w) {
                const float* base = gsm + w * (32 * 36) + cb;
                ii += base[(0 * 8 + cu) * 36];
                ff += base[(1 * 8 + cu) * 36];
                g2 += base[(2 * 8 + cu) * 36];
                oo += base[(3 * 8 + cu) * 36];
            }
            float cn = sigf(ff) * c + sigf(ii) * tanhf(g2);
            float hn = sigf(oo) * tanhf(cn);
            float hold = hs[(u0 + cu) * 32 + cb];
            float hw = m ? hn : hold;
            c = m ? cn : c;
            g_h[dir][1 - pp][u0 + cu][cb] = hw;
            ys[((size_t)(cb * SEQ + s)) * (2 * HL) + dir * HL + u0 + cu] = m ? hn : 0.f;
        }

        __syncthreads();
        if (tid == 0) {
            __threadfence();
            atomicAdd(&g_bar[dir], 1u);
            unsigned tgt = 64u * (unsigned)(t + 1);
            while (*(volatile unsigned*)&g_bar[dir] < tgt) { }
            __threadfence();
        }
        __syncthreads();
    }
}

// ---------------------------------------------------------------------------
// Launch
// ---------------------------------------------------------------------------
extern "C" void kernel_launch(void* const* d_in, const int* in_sizes, int n_in,
                              void* d_out, int out_size)
{
    const float* seq_out = (const float*)d_in[0];
    const int* attn_mask = (const int*)d_in[1];
    const int* lang_raw = (const int*)d_in[2];
    const float* W1 = (const float*)d_in[3];
    const float* b1 = (const float*)d_in[4];
    const float* ln_g = (const float*)d_in[5];
    const float* ln_b = (const float*)d_in[6];
    const float* W2 = (const float*)d_in[7];
    const float* b2 = (const float*)d_in[8];
    const float* Wih_f = (const float*)d_in[9];
    const float* Whh_f = (const float*)d_in[10];
    const float* b_f = (const float*)d_in[11];
    const float* Wih_b = (const float*)d_in[12];
    const float* Whh_b = (const float*)d_in[13];
    const float* b_b = (const float*)d_in[14];
    const float* Wp = (const float*)d_in[15];
    const float* bp = (const float*)d_in[16];
    float* out = (float*)d_out;

    float* h1;       cudaGetSymbolAddress((void**)&h1, g_h1);
    float* adapted;  cudaGetSymbolAddress((void**)&adapted, g_adapted);
    float* gates_f;  cudaGetSymbolAddress((void**)&gates_f, g_gates_f);
    float* gates_b;  cudaGetSymbolAddress((void**)&gates_b, g_gates_b);
    float* ys;       cudaGetSymbolAddress((void**)&ys, g_ys);
    float* Wt1;      cudaGetSymbolAddress((void**)&Wt1, g_Wt1);
    float* Wt2;      cudaGetSymbolAddress((void**)&Wt2, g_Wt2);
    void* h_ptr;     cudaGetSymbolAddress(&h_ptr, g_h);
    void* bar_ptr;   cudaGetSymbolAddress(&bar_ptr, g_bar);

    cudaFuncSetAttribute(lstm_kernel,
                         cudaFuncAttributeMaxDynamicSharedMemorySize,
                         LSTM_SMEM_BYTES);

    cudaMemsetAsync(h_ptr, 0, sizeof(float) * 2 * 2 * HL * BATCH);
    cudaMemsetAsync(bar_ptr, 0, sizeof(unsigned) * 2);

    // 0) normalize language ids + transpose adapter weights
    lang_normalize_kernel<<<1, 32>>>(lang_raw);
    transpose_w_kernel<<<dim3(32, 32, NLANG), 256>>>(W1, Wt1);
    transpose_w_kernel<<<dim3(32, 32, NLANG), 256>>>(W2, Wt2);
    // 1) adapter GEMM1 (3xtf32)
    mma_adapter_kernel<<<dim3(HID / 128, SEQ / 128, BATCH), 256>>>(
        seq_out, Wt1, b1, h1);
    // 2) LN + ReLU
    ln_relu_kernel<<<BATCH * SEQ, 256>>>(h1, ln_g, ln_b);
    // 3) adapter GEMM2 (3xtf32)
    mma_adapter_kernel<<<dim3(HID / 128, SEQ / 128, BATCH), 256>>>(
        h1, Wt2, b2, adapted);
    // 4) input-gate precompute (single-pass tf32), both directions
    mma_nt1x_kernel<<<dim3(4 * HL / 128, BATCH * SEQ / 128), 256>>>(
        adapted, Wih_f, b_f, gates_f, HID, 4 * HL);
    mma_nt1x_kernel<<<dim3(4 * HL / 128, BATCH * SEQ / 128), 256>>>(
        adapted, Wih_b, b_b, gates_b, HID, 4 * HL);
    // 5) persistent BiLSTM
    lstm_kernel<<<dim3(64, 2), 256, LSTM_SMEM_BYTES>>>(
        gates_f, gates_b, Whh_f, Whh_b, attn_mask, ys);
    // 6) projection (fp32 SIMT)
    nt_gemm_kernel<<<dim3(EOUT / TS_BN, BATCH * SEQ / TS_BM), 256>>>(
        ys, Wp, bp, out, 2 * HL, EOUT);
}

// round 15
// speedup vs baseline: 1.4418x; 1.1502x over previous
#include <cuda_runtime.h>
#include <cuda_bf16.h>
#include <cstdint>

// Problem constants
#define BATCH 32
#define SEQ   256
#define HID   1024
#define HL    512
#define EOUT  256
#define NLANG 5

typedef unsigned long long ull;

// ---------------------------------------------------------------------------
// Scratch (device globals — no allocation allowed)
// ---------------------------------------------------------------------------
__device__ float g_h1[BATCH * SEQ * HID];
__device__ float g_adapted[BATCH * SEQ * HID];
__device__ float g_gates_f[BATCH * SEQ * 4 * HL];
__device__ float g_gates_b[BATCH * SEQ * 4 * HL];
__device__ float g_ys[BATCH * SEQ * 2 * HL];
__device__ float g_h[2][2][HL][BATCH];     // dir, pingpong, UNIT, BATCH
__device__ unsigned g_bar[2];
__device__ int   g_lang[BATCH];
__device__ float g_Wt1[NLANG * HID * HID];   // W1^T: [l][n][k]
__device__ float g_Wt2[NLANG * HID * HID];   // W2^T

// ---------------------------------------------------------------------------
// tf32 + mma.sync helpers
// ---------------------------------------------------------------------------
__device__ __forceinline__ uint32_t tf32_cvt(float x)
{
    uint32_t h;
    asm("cvt.rna.tf32.f32 %0, %1;" : "=r"(h) : "f"(x));
    return h;
}

__device__ __forceinline__ void mma8(float* d, const uint32_t* a, const uint32_t* b)
{
    asm volatile(
        "mma.sync.aligned.m16n8k8.row.col.f32.tf32.tf32.f32 "
        "{%0,%1,%2,%3}, {%4,%5,%6,%7}, {%8,%9}, {%0,%1,%2,%3};"
        : "+f"(d[0]), "+f"(d[1]), "+f"(d[2]), "+f"(d[3])
        : "r"(a[0]), "r"(a[1]), "r"(a[2]), "r"(a[3]), "r"(b[0]), "r"(b[1]));
}

__device__ __forceinline__ void ffma2(ull& d, ull a, ull b)
{
    asm("fma.rn.f32x2 %0, %1, %2, %0;" : "+l"(d) : "l"(a), "l"(b));
}

#define BKC 16
#define MM_PAD1 136

// ---------------------------------------------------------------------------
// Single-pass tf32 NT GEMM body: C[128,128] = A[128,K] @ B[128,K]^T + bias
// 256 threads, 8 warps (4M x 2N), warp tile 32x64. ~2-3e-4 per-stage accuracy.
// ---------------------------------------------------------------------------
__device__ __forceinline__ void mma_nt_body_1x(
    const float* __restrict__ At, int lda,
    const float* __restrict__ Bt, int ldb,
    const float* __restrict__ bias_t,
    float* __restrict__ Ct, int ldc,
    int K)
{
    __shared__ uint32_t As1[BKC][MM_PAD1];
    __shared__ uint32_t Bs1[BKC][MM_PAD1];

    int tid = threadIdx.x;
    int lane = tid & 31, wid = tid >> 5;
    int warpM = wid & 3, warpN = wid >> 2;
    int m0 = warpM * 32, n0w = warpN * 64;
    int g = lane >> 2, t4 = lane & 3;

    int r = tid >> 1, cq = (tid & 1) * 8;

    float acc[2][8][4];
#pragma unroll
    for (int mi = 0; mi < 2; mi++)
#pragma unroll
        for (int ni = 0; ni < 8; ni++)
#pragma unroll
            for (int q = 0; q < 4; q++) acc[mi][ni][q] = 0.f;

    float4 pa0 = *(const float4*)(At + (size_t)r * lda + cq);
    float4 pa1 = *(const float4*)(At + (size_t)r * lda + cq + 4);
    float4 pb0 = *(const float4*)(Bt + (size_t)r * ldb + cq);
    float4 pb1 = *(const float4*)(Bt + (size_t)r * ldb + cq + 4);

    int nch = K >> 4;
    for (int c = 0; c < nch; ++c) {
        __syncthreads();
        {
            float av[8] = {pa0.x, pa0.y, pa0.z, pa0.w, pa1.x, pa1.y, pa1.z, pa1.w};
            float bv[8] = {pb0.x, pb0.y, pb0.z, pb0.w, pb1.x, pb1.y, pb1.z, pb1.w};
#pragma unroll
            for (int i = 0; i < 8; i++) {
                As1[cq + i][r] = tf32_cvt(av[i]);
                Bs1[cq + i][r] = tf32_cvt(bv[i]);
            }
        }
        __syncthreads();
        if (c + 1 < nch) {
            int k0 = (c + 1) * BKC;
            pa0 = *(const float4*)(At + (size_t)r * lda + k0 + cq);
            pa1 = *(const float4*)(At + (size_t)r * lda + k0 + cq + 4);
            pb0 = *(const float4*)(Bt + (size_t)r * ldb + k0 + cq);
            pb1 = *(const float4*)(Bt + (size_t)r * ldb + k0 + cq + 4);
        }
#pragma unroll
        for (int ks = 0; ks < BKC; ks += 8) {
            uint32_t ah[2][4];
#pragma unroll
            for (int mi = 0; mi < 2; mi++) {
                int m = m0 + mi * 16;
                ah[mi][0] = As1[ks + t4][m + g];
                ah[mi][1] = As1[ks + t4][m + g + 8];
                ah[mi][2] = As1[ks + t4 + 4][m + g];
                ah[mi][3] = As1[ks + t4 + 4][m + g + 8];
            }
#pragma unroll
            for (int ni = 0; ni < 8; ni++) {
                int n = n0w + ni * 8 + g;
                uint32_t bh[2];
                bh[0] = Bs1[ks + t4][n];
                bh[1] = Bs1[ks + t4 + 4][n];
                mma8(acc[0][ni], ah[0], bh);
                mma8(acc[1][ni], ah[1], bh);
            }
        }
    }

#pragma unroll
    for (int mi = 0; mi < 2; mi++) {
#pragma unroll
        for (int ni = 0; ni < 8; ni++) {
            int row0 = m0 + mi * 16 + g;
            int col = n0w + ni * 8 + 2 * t4;
            float2 b2 = *(const float2*)&bias_t[col];
            float2 o0 = {acc[mi][ni][0] + b2.x, acc[mi][ni][1] + b2.y};
            float2 o1 = {acc[mi][ni][2] + b2.x, acc[mi][ni][3] + b2.y};
            *(float2*)&Ct[(size_t)row0 * ldc + col] = o0;
            *(float2*)&Ct[(size_t)(row0 + 8) * ldc + col] = o1;
        }
    }
}

// Adapter GEMM (language-selected W): single-pass tf32
__global__ void __launch_bounds__(256, 2) mma_adapter_kernel(
    const float* __restrict__ Abase, const float* __restrict__ Wt,
    const float* __restrict__ ball, float* __restrict__ Cbase)
{
    int b = blockIdx.z;
    int l = g_lang[b];
    const float* At = Abase + (size_t)b * SEQ * HID + (size_t)blockIdx.y * 128 * HID;
    const float* Bt = Wt + (size_t)l * HID * HID + (size_t)blockIdx.x * 128 * HID;
    const float* bias_t = ball + (size_t)l * HID + blockIdx.x * 128;
    float* Ct = Cbase + (size_t)b * SEQ * HID + (size_t)blockIdx.y * 128 * HID
              + blockIdx.x * 128;
    mma_nt_body_1x(At, HID, Bt, HID, bias_t, Ct, HID, HID);
}

// Both gate GEMMs in ONE launch: blockIdx.z = direction
__global__ void __launch_bounds__(256, 2) mma_gates_kernel(
    const float* __restrict__ A,
    const float* __restrict__ Wf, const float* __restrict__ Wb,
    const float* __restrict__ bf, const float* __restrict__ bb,
    float* __restrict__ Cf, float* __restrict__ Cb)
{
    int dir = blockIdx.z;
    const float* B = dir ? Wb : Wf;
    const float* bias = dir ? bb : bf;
    float* C = dir ? Cb : Cf;
    const float* At = A + (size_t)blockIdx.y * 128 * HID;
    const float* Bt = B + (size_t)blockIdx.x * 128 * HID;
    const float* bias_t = bias + blockIdx.x * 128;
    float* Ct = C + (size_t)blockIdx.y * 128 * (4 * HL) + blockIdx.x * 128;
    mma_nt_body_1x(At, HID, Bt, HID, bias_t, Ct, 4 * HL, HID);
}

// ---------------------------------------------------------------------------
// W transpose: Wt[l][n][k] = W[l][k][n]
// ---------------------------------------------------------------------------
__global__ void __launch_bounds__(256) transpose_w_kernel(
    const float* __restrict__ W, float* __restrict__ Wt)
{
    __shared__ float tile[32][33];
    int l = blockIdx.z;
    int k0 = blockIdx.y * 32, n0 = blockIdx.x * 32;
    const float* Win = W + (size_t)l * HID * HID;
    float* Wout = Wt + (size_t)l * HID * HID;
    int x = threadIdx.x & 31, y = (threadIdx.x >> 5) * 4;
#pragma unroll
    for (int i = 0; i < 4; i++)
        tile[y + i][x] = Win[(size_t)(k0 + y + i) * HID + n0 + x];
    __syncthreads();
#pragma unroll
    for (int i = 0; i < 4; i++)
        Wout[(size_t)(n0 + y + i) * HID + k0 + x] = tile[x][y + i];
}

// ---------------------------------------------------------------------------
// Language-id normalization (dtype-robust)
// ---------------------------------------------------------------------------
__global__ void lang_normalize_kernel(const int* __restrict__ raw)
{
    __shared__ int first[32];
    int t = threadIdx.x;
    first[t] = raw[t];
    __syncwarp();
    bool odd_zero = true;
#pragma unroll
    for (int i = 1; i < 32; i += 2) odd_zero &= (first[i] == 0);
    int v = odd_zero ? raw[2 * t] : first[t];
    v = v < 0 ? 0 : (v >= NLANG ? NLANG - 1 : v);
    g_lang[t] = v;
}

// ---------------------------------------------------------------------------
// fp32 SIMT NT GEMM (projection only)
// ---------------------------------------------------------------------------
#define TS_BM 128
#define TS_BN 64
#define TS_BK 16

__global__ void __launch_bounds__(256) nt_gemm_kernel(
    const float* __restrict__ A, const float* __restrict__ Bm,
    const float* __restrict__ bias, float* __restrict__ C,
    int K, int ldc)
{
    __shared__ float As[TS_BK][TS_BM + 4];
    __shared__ float Bs[TS_BK][TS_BN];
    int row0 = blockIdx.y * TS_BM, col0 = blockIdx.x * TS_BN;
    int tid = threadIdx.x;
    int tx = tid & 15, ty = tid >> 4;
    float acc[8][4];
#pragma unroll
    for (int i = 0; i < 8; i++)
#pragma unroll
        for (int j = 0; j < 4; j++) acc[i][j] = 0.f;

    for (int k0 = 0; k0 < K; k0 += TS_BK) {
#pragma unroll
        for (int q = 0; q < 2; ++q) {
            int slot = tid + q * 256;
            int rr = slot >> 2;
            int kk = (slot & 3) * 4;
            float4 v = *(const float4*)&A[(size_t)(row0 + rr) * K + k0 + kk];
            As[kk + 0][rr] = v.x; As[kk + 1][rr] = v.y;
            As[kk + 2][rr] = v.z; As[kk + 3][rr] = v.w;
        }
        {
            int n = tid >> 2;
            int kk4 = (tid & 3) * 4;
            float4 v = *(const float4*)&Bm[(size_t)(col0 + n) * K + k0 + kk4];
            Bs[kk4 + 0][n] = v.x; Bs[kk4 + 1][n] = v.y;
            Bs[kk4 + 2][n] = v.z; Bs[kk4 + 3][n] = v.w;
        }
        __syncthreads();
#pragma unroll
        for (int kk = 0; kk < TS_BK; ++kk) {
            float a[8];
#pragma unroll
            for (int i = 0; i < 8; i++) a[i] = As[kk][ty * 8 + i];
            float4 bv = *(const float4*)&Bs[kk][tx * 4];
#pragma unroll
            for (int i = 0; i < 8; i++) {
                acc[i][0] += a[i] * bv.x; acc[i][1] += a[i] * bv.y;
                acc[i][2] += a[i] * bv.z; acc[i][3] += a[i] * bv.w;
            }
        }
        __syncthreads();
    }
    float4 bb = *(const float4*)&bias[col0 + tx * 4];
#pragma unroll
    for (int i = 0; i < 8; i++) {
        float4 o;
        o.x = acc[i][0] + bb.x; o.y = acc[i][1] + bb.y;
        o.z = acc[i][2] + bb.z; o.w = acc[i][3] + bb.w;
        *(float4*)&C[(size_t)(row0 + ty * 8 + i) * ldc + col0 + tx * 4] = o;
    }
}

// ---------------------------------------------------------------------------
// LayerNorm (biased var) + ReLU, in place
// ---------------------------------------------------------------------------
__global__ void __launch_bounds__(256) ln_relu_kernel(
    float* __restrict__ h, const float* __restrict__ ln_g_all,
    const float* __restrict__ ln_b_all)
{
    int row = blockIdx.x;
    int b = row >> 8;
    int l = g_lang[b];
    float4* x = (float4*)(h + (size_t)row * HID);
    float4 v = x[threadIdx.x];
    float s = v.x + v.y + v.z + v.w;
    float ss = v.x * v.x + v.y * v.y + v.z * v.z + v.w * v.w;
#pragma unroll
    for (int o = 16; o; o >>= 1) {
        s += __shfl_xor_sync(0xffffffffu, s, o);
        ss += __shfl_xor_sync(0xffffffffu, ss, o);
    }
    __shared__ float rs[8], rss[8];
    __shared__ float smean, sinv;
    int w = threadIdx.x >> 5;
    if ((threadIdx.x & 31) == 0) { rs[w] = s; rss[w] = ss; }
    __syncthreads();
    if (threadIdx.x == 0) {
        float S = 0.f, SS = 0.f;
#pragma unroll
        for (int i = 0; i < 8; i++) { S += rs[i]; SS += rss[i]; }
        float mean = S * (1.f / 1024.f);
        float var = SS * (1.f / 1024.f) - mean * mean;
        smean = mean;
        sinv = rsqrtf(var + 1e-5f);
    }
    __syncthreads();
    float mean = smean, inv = sinv;
    float4 g4 = *((const float4*)(ln_g_all + (size_t)l * HID) + threadIdx.x);
    float4 b4 = *((const float4*)(ln_b_all + (size_t)l * HID) + threadIdx.x);
    v.x = fmaxf((v.x - mean) * inv * g4.x + b4.x, 0.f);
    v.y = fmaxf((v.y - mean) * inv * g4.y + b4.y, 0.f);
    v.z = fmaxf((v.z - mean) * inv * g4.z + b4.z, 0.f);
    v.w = fmaxf((v.w - mean) * inv * g4.w + b4.w, 0.f);
    x[threadIdx.x] = v;
}

// ---------------------------------------------------------------------------
// Persistent BiLSTM — register-resident Whh + broadcast h + warp-local staging.
// ---------------------------------------------------------------------------
#define LSTM_HS_FLOATS (512 * 32)                 // 64 KB
#define LSTM_GS_FLOATS (8 * 32 * 36)              // 36 KB
#define LSTM_SMEM_BYTES ((LSTM_HS_FLOATS + LSTM_GS_FLOATS) * 4)

__device__ __forceinline__ float sigf(float x) { return 1.f / (1.f + expf(-x)); }

__global__ void __launch_bounds__(256, 1) lstm_kernel(
    const float* __restrict__ gates_f, const float* __restrict__ gates_b,
    const float* __restrict__ Whh_fw, const float* __restrict__ Whh_bw,
    const int* __restrict__ mask, float* __restrict__ ys)
{
    extern __shared__ float sm[];
    float* hs = sm;                                // [512][32]
    float* gsm = sm + LSTM_HS_FLOATS;              // [8][32][36]

    int tid = threadIdx.x;
    int dir = blockIdx.y;
    int u0 = blockIdx.x * 8;
    const float* Whh = dir ? Whh_bw : Whh_fw;
    const float* G = dir ? gates_b : gates_f;

    int lane = tid & 31, wp = tid >> 5;
    int grow = (lane >> 3) * HL + u0 + (lane & 7);
    int ks = wp * 64;

    float w_reg[64];
    {
        const float4* wsrc = (const float4*)(Whh + (size_t)grow * HL + ks);
#pragma unroll
        for (int j = 0; j < 16; j++) {
            float4 v = wsrc[j];
            w_reg[4 * j + 0] = v.x; w_reg[4 * j + 1] = v.y;
            w_reg[4 * j + 2] = v.z; w_reg[4 * j + 3] = v.w;
        }
    }

    int cu = tid >> 5;
    int cb = tid & 31;
    float c = 0.f;

    float* grow_out = gsm + (wp * 32 + lane) * 36;
    float4* hdst_seg = (float4*)(hs + ks * 32);

    for (int t = 0; t < SEQ; ++t) {
        int s = dir ? (SEQ - 1 - t) : t;
        int pp = t & 1;

        size_t gbase = ((size_t)(cb * SEQ + s)) * (4 * HL) + u0 + cu;
        float gi = G[gbase];
        float gf = G[gbase + 512];
        float gg = G[gbase + 1024];
        float go = G[gbase + 1536];
        int m = mask[cb * SEQ + s];

        {
            const float4* hsrc = (const float4*)(&g_h[dir][pp][0][0]) + ks * 8;
#pragma unroll
            for (int i = 0; i < 16; ++i)
                hdst_seg[lane + 32 * i] = __ldcg(hsrc + lane + 32 * i);
        }
        __syncwarp();

        ull acc[16];
#pragma unroll
        for (int j = 0; j < 16; j++) acc[j] = 0ull;
#pragma unroll
        for (int k = 0; k < 64; ++k) {
            uint32_t wb = __float_as_uint(w_reg[k]);
            ull w2;
            asm("mov.b64 %0, {%1, %1};" : "=l"(w2) : "r"(wb));
            const ulonglong2* hp = (const ulonglong2*)(hs + (ks + k) * 32);
#pragma unroll
            for (int j = 0; j < 8; ++j) {
                ulonglong2 h2 = hp[j];
                ffma2(acc[2 * j], w2, h2.x);
                ffma2(acc[2 * j + 1], w2, h2.y);
            }
        }
#pragma unroll
        for (int j = 0; j < 8; ++j) {
            ulonglong2 o;
            o.x = acc[2 * j]; o.y = acc[2 * j + 1];
            *(ulonglong2*)(grow_out + 4 * j) = o;
        }
        __syncthreads();

        {
            float ii = gi, ff = gf, g2 = gg, oo = go;
#pragma unroll
            for (int w = 0; w < 8; ++w) {
                const float* base = gsm + w * (32 * 36) + cb;
                ii += base[(0 * 8 + cu) * 36];
                ff += base[(1 * 8 + cu) * 36];
                g2 += base[(2 * 8 + cu) * 36];
                oo += base[(3 * 8 + cu) * 36];
            }
            float cn = sigf(ff) * c + sigf(ii) * tanhf(g2);
            float hn = sigf(oo) * tanhf(cn);
            float hold = hs[(u0 + cu) * 32 + cb];
            float hw = m ? hn : hold;
            c = m ? cn : c;
            g_h[dir][1 - pp][u0 + cu][cb] = hw;
            ys[((size_t)(cb * SEQ + s)) * (2 * HL) + dir * HL + u0 + cu] = m ? hn : 0.f;
        }

        __syncthreads();
        if (tid == 0) {
            __threadfence();
            atomicAdd(&g_bar[dir], 1u);
            unsigned tgt = 64u * (unsigned)(t + 1);
            while (*(volatile unsigned*)&g_bar[dir] < tgt) { }
            __threadfence();
        }
        __syncthreads();
    }
}

// ---------------------------------------------------------------------------
// Launch
// ---------------------------------------------------------------------------
extern "C" void kernel_launch(void* const* d_in, const int* in_sizes, int n_in,
                              void* d_out, int out_size)
{
    const float* seq_out = (const float*)d_in[0];
    const int* attn_mask = (const int*)d_in[1];
    const int* lang_raw = (const int*)d_in[2];
    const float* W1 = (const float*)d_in[3];
    const float* b1 = (const float*)d_in[4];
    const float* ln_g = (const float*)d_in[5];
    const float* ln_b = (const float*)d_in[6];
    const float* W2 = (const float*)d_in[7];
    const float* b2 = (const float*)d_in[8];
    const float* Wih_f = (const float*)d_in[9];
    const float* Whh_f = (const float*)d_in[10];
    const float* b_f = (const float*)d_in[11];
    const float* Wih_b = (const float*)d_in[12];
    const float* Whh_b = (const float*)d_in[13];
    const float* b_b = (const float*)d_in[14];
    const float* Wp = (const float*)d_in[15];
    const float* bp = (const float*)d_in[16];
    float* out = (float*)d_out;

    float* h1;       cudaGetSymbolAddress((void**)&h1, g_h1);
    float* adapted;  cudaGetSymbolAddress((void**)&adapted, g_adapted);
    float* gates_f;  cudaGetSymbolAddress((void**)&gates_f, g_gates_f);
    float* gates_b;  cudaGetSymbolAddress((void**)&gates_b, g_gates_b);
    float* ys;       cudaGetSymbolAddress((void**)&ys, g_ys);
    float* Wt1;      cudaGetSymbolAddress((void**)&Wt1, g_Wt1);
    float* Wt2;      cudaGetSymbolAddress((void**)&Wt2, g_Wt2);
    void* h_ptr;     cudaGetSymbolAddress(&h_ptr, g_h);
    void* bar_ptr;   cudaGetSymbolAddress(&bar_ptr, g_bar);

    cudaFuncSetAttribute(lstm_kernel,
                         cudaFuncAttributeMaxDynamicSharedMemorySize,
                         LSTM_SMEM_BYTES);

    cudaMemsetAsync(h_ptr, 0, sizeof(float) * 2 * 2 * HL * BATCH);
    cudaMemsetAsync(bar_ptr, 0, sizeof(unsigned) * 2);

    // 0) normalize language ids + transpose adapter weights
    lang_normalize_kernel<<<1, 32>>>(lang_raw);
    transpose_w_kernel<<<dim3(32, 32, NLANG), 256>>>(W1, Wt1);
    transpose_w_kernel<<<dim3(32, 32, NLANG), 256>>>(W2, Wt2);
    // 1) adapter GEMM1 (1x tf32)
    mma_adapter_kernel<<<dim3(HID / 128, SEQ / 128, BATCH), 256>>>(
        seq_out, Wt1, b1, h1);
    // 2) LN + ReLU
    ln_relu_kernel<<<BATCH * SEQ, 256>>>(h1, ln_g, ln_b);
    // 3) adapter GEMM2 (1x tf32)
    mma_adapter_kernel<<<dim3(HID / 128, SEQ / 128, BATCH), 256>>>(
        h1, Wt2, b2, adapted);
    // 4) input-gate precompute (1x tf32), BOTH directions in one launch
    mma_gates_kernel<<<dim3(4 * HL / 128, BATCH * SEQ / 128, 2), 256>>>(
        adapted, Wih_f, Wih_b, b_f, b_b, gates_f, gates_b);
    // 5) persistent BiLSTM
    lstm_kernel<<<dim3(64, 2), 256, LSTM_SMEM_BYTES>>>(
        gates_f, gates_b, Whh_f, Whh_b, attn_mask, ys);
    // 6) projection (fp32 SIMT)
    nt_gemm_kernel<<<dim3(EOUT / TS_BN, BATCH * SEQ / TS_BM), 256>>>(
        ys, Wp, bp, out, 2 * HL, EOUT);
}

// round 16
// speedup vs baseline: 1.5103x; 1.0475x over previous
#include <cuda_runtime.h>
#include <cuda_bf16.h>
#include <cstdint>

// Problem constants
#define BATCH 32
#define SEQ   256
#define HID   1024
#define HL    512
#define EOUT  256
#define NLANG 5

typedef unsigned long long ull;

// ---------------------------------------------------------------------------
// Scratch (device globals — no allocation allowed)
// ---------------------------------------------------------------------------
__device__ float g_h1[BATCH * SEQ * HID];
__device__ float g_adapted[BATCH * SEQ * HID];
__device__ float g_gates_f[BATCH * SEQ * 4 * HL];
__device__ float g_gates_b[BATCH * SEQ * 4 * HL];
__device__ float g_ys[BATCH * SEQ * 2 * HL];
__device__ float g_h[2][2][HL][BATCH];     // dir, pingpong, UNIT, BATCH
__device__ unsigned g_bar[2];
__device__ int   g_lang[BATCH];
__device__ float g_Wt1[NLANG * HID * HID];   // W1^T: [l][n][k]
__device__ float g_Wt2[NLANG * HID * HID];   // W2^T

// ---------------------------------------------------------------------------
// tf32 + mma.sync helpers
// ---------------------------------------------------------------------------
__device__ __forceinline__ uint32_t tf32_cvt(float x)
{
    uint32_t h;
    asm("cvt.rna.tf32.f32 %0, %1;" : "=r"(h) : "f"(x));
    return h;
}

__device__ __forceinline__ void mma8(float* d, const uint32_t* a, const uint32_t* b)
{
    asm volatile(
        "mma.sync.aligned.m16n8k8.row.col.f32.tf32.tf32.f32 "
        "{%0,%1,%2,%3}, {%4,%5,%6,%7}, {%8,%9}, {%0,%1,%2,%3};"
        : "+f"(d[0]), "+f"(d[1]), "+f"(d[2]), "+f"(d[3])
        : "r"(a[0]), "r"(a[1]), "r"(a[2]), "r"(a[3]), "r"(b[0]), "r"(b[1]));
}

__device__ __forceinline__ void ffma2(ull& d, ull a, ull b)
{
    asm("fma.rn.f32x2 %0, %1, %2, %0;" : "+l"(d) : "l"(a), "l"(b));
}

// release/acquire barrier primitives (no full MEMBAR)
__device__ __forceinline__ void bar_arrive(unsigned* p)
{
    unsigned old;
    asm volatile("atom.add.release.gpu.global.u32 %0, [%1], 1;"
                 : "=r"(old) : "l"(p) : "memory");
}
__device__ __forceinline__ unsigned bar_poll(const unsigned* p)
{
    unsigned v;
    asm volatile("ld.acquire.gpu.global.u32 %0, [%1];" : "=r"(v) : "l"(p) : "memory");
    return v;
}

#define BKC 16
#define MM_PAD1 136

// ---------------------------------------------------------------------------
// Single-pass tf32 NT GEMM body, DOUBLE-BUFFERED (one sync per chunk):
// C[128,128] = A[128,K] @ B[128,K]^T + bias
// 256 threads, 8 warps (4M x 2N), warp tile 32x64.
// ---------------------------------------------------------------------------
__device__ __forceinline__ void mma_nt_body_1x(
    const float* __restrict__ At, int lda,
    const float* __restrict__ Bt, int ldb,
    const float* __restrict__ bias_t,
    float* __restrict__ Ct, int ldc,
    int K)
{
    __shared__ uint32_t As1[2][BKC][MM_PAD1];
    __shared__ uint32_t Bs1[2][BKC][MM_PAD1];

    int tid = threadIdx.x;
    int lane = tid & 31, wid = tid >> 5;
    int warpM = wid & 3, warpN = wid >> 2;
    int m0 = warpM * 32, n0w = warpN * 64;
    int g = lane >> 2, t4 = lane & 3;

    int r = tid >> 1, cq = (tid & 1) * 8;
    const float* Arow = At + (size_t)r * lda + cq;
    const float* Brow = Bt + (size_t)r * ldb + cq;

    float acc[2][8][4];
#pragma unroll
    for (int mi = 0; mi < 2; mi++)
#pragma unroll
        for (int ni = 0; ni < 8; ni++)
#pragma unroll
            for (int q = 0; q < 4; q++) acc[mi][ni][q] = 0.f;

    int nch = K >> 4;
    float4 pa0, pa1, pb0, pb1;

    // chunk 0 -> buffer 0
    pa0 = *(const float4*)(Arow);
    pa1 = *(const float4*)(Arow + 4);
    pb0 = *(const float4*)(Brow);
    pb1 = *(const float4*)(Brow + 4);
    {
        As1[0][cq + 0][r] = tf32_cvt(pa0.x); As1[0][cq + 1][r] = tf32_cvt(pa0.y);
        As1[0][cq + 2][r] = tf32_cvt(pa0.z); As1[0][cq + 3][r] = tf32_cvt(pa0.w);
        As1[0][cq + 4][r] = tf32_cvt(pa1.x); As1[0][cq + 5][r] = tf32_cvt(pa1.y);
        As1[0][cq + 6][r] = tf32_cvt(pa1.z); As1[0][cq + 7][r] = tf32_cvt(pa1.w);
        Bs1[0][cq + 0][r] = tf32_cvt(pb0.x); Bs1[0][cq + 1][r] = tf32_cvt(pb0.y);
        Bs1[0][cq + 2][r] = tf32_cvt(pb0.z); Bs1[0][cq + 3][r] = tf32_cvt(pb0.w);
        Bs1[0][cq + 4][r] = tf32_cvt(pb1.x); Bs1[0][cq + 5][r] = tf32_cvt(pb1.y);
        Bs1[0][cq + 6][r] = tf32_cvt(pb1.z); Bs1[0][cq + 7][r] = tf32_cvt(pb1.w);
    }
    // chunk 1 -> regs
    if (nch > 1) {
        pa0 = *(const float4*)(Arow + BKC);
        pa1 = *(const float4*)(Arow + BKC + 4);
        pb0 = *(const float4*)(Brow + BKC);
        pb1 = *(const float4*)(Brow + BKC + 4);
    }
    __syncthreads();

    for (int c = 0; c < nch; ++c) {
        int buf = c & 1;
        // store chunk c+1 (regs) into the idle buffer
        if (c + 1 < nch) {
            int ob = buf ^ 1;
            As1[ob][cq + 0][r] = tf32_cvt(pa0.x); As1[ob][cq + 1][r] = tf32_cvt(pa0.y);
            As1[ob][cq + 2][r] = tf32_cvt(pa0.z); As1[ob][cq + 3][r] = tf32_cvt(pa0.w);
            As1[ob][cq + 4][r] = tf32_cvt(pa1.x); As1[ob][cq + 5][r] = tf32_cvt(pa1.y);
            As1[ob][cq + 6][r] = tf32_cvt(pa1.z); As1[ob][cq + 7][r] = tf32_cvt(pa1.w);
            Bs1[ob][cq + 0][r] = tf32_cvt(pb0.x); Bs1[ob][cq + 1][r] = tf32_cvt(pb0.y);
            Bs1[ob][cq + 2][r] = tf32_cvt(pb0.z); Bs1[ob][cq + 3][r] = tf32_cvt(pb0.w);
            Bs1[ob][cq + 4][r] = tf32_cvt(pb1.x); Bs1[ob][cq + 5][r] = tf32_cvt(pb1.y);
            Bs1[ob][cq + 6][r] = tf32_cvt(pb1.z); Bs1[ob][cq + 7][r] = tf32_cvt(pb1.w);
        }
        // prefetch chunk c+2 into regs (overlaps mma)
        if (c + 2 < nch) {
            int k0 = (c + 2) * BKC;
            pa0 = *(const float4*)(Arow + k0);
            pa1 = *(const float4*)(Arow + k0 + 4);
            pb0 = *(const float4*)(Brow + k0);
            pb1 = *(const float4*)(Brow + k0 + 4);
        }
        // mma on chunk c (buffer buf)
#pragma unroll
        for (int ks = 0; ks < BKC; ks += 8) {
            uint32_t ah[2][4];
#pragma unroll
            for (int mi = 0; mi < 2; mi++) {
                int m = m0 + mi * 16;
                ah[mi][0] = As1[buf][ks + t4][m + g];
                ah[mi][1] = As1[buf][ks + t4][m + g + 8];
                ah[mi][2] = As1[buf][ks + t4 + 4][m + g];
                ah[mi][3] = As1[buf][ks + t4 + 4][m + g + 8];
            }
#pragma unroll
            for (int ni = 0; ni < 8; ni++) {
                int n = n0w + ni * 8 + g;
                uint32_t bh[2];
                bh[0] = Bs1[buf][ks + t4][n];
                bh[1] = Bs1[buf][ks + t4 + 4][n];
                mma8(acc[0][ni], ah[0], bh);
                mma8(acc[1][ni], ah[1], bh);
            }
        }
        __syncthreads();
    }

#pragma unroll
    for (int mi = 0; mi < 2; mi++) {
#pragma unroll
        for (int ni = 0; ni < 8; ni++) {
            int row0 = m0 + mi * 16 + g;
            int col = n0w + ni * 8 + 2 * t4;
            float2 b2 = *(const float2*)&bias_t[col];
            float2 o0 = {acc[mi][ni][0] + b2.x, acc[mi][ni][1] + b2.y};
            float2 o1 = {acc[mi][ni][2] + b2.x, acc[mi][ni][3] + b2.y};
            *(float2*)&Ct[(size_t)row0 * ldc + col] = o0;
            *(float2*)&Ct[(size_t)(row0 + 8) * ldc + col] = o1;
        }
    }
}

// Adapter GEMM (language-selected W): single-pass tf32
__global__ void __launch_bounds__(256, 2) mma_adapter_kernel(
    const float* __restrict__ Abase, const float* __restrict__ Wt,
    const float* __restrict__ ball, float* __restrict__ Cbase)
{
    int b = blockIdx.z;
    int l = g_lang[b];
    const float* At = Abase + (size_t)b * SEQ * HID + (size_t)blockIdx.y * 128 * HID;
    const float* Bt = Wt + (size_t)l * HID * HID + (size_t)blockIdx.x * 128 * HID;
    const float* bias_t = ball + (size_t)l * HID + blockIdx.x * 128;
    float* Ct = Cbase + (size_t)b * SEQ * HID + (size_t)blockIdx.y * 128 * HID
              + blockIdx.x * 128;
    mma_nt_body_1x(At, HID, Bt, HID, bias_t, Ct, HID, HID);
}

// Both gate GEMMs in ONE launch: blockIdx.z = direction
__global__ void __launch_bounds__(256, 2) mma_gates_kernel(
    const float* __restrict__ A,
    const float* __restrict__ Wf, const float* __restrict__ Wb,
    const float* __restrict__ bf, const float* __restrict__ bb,
    float* __restrict__ Cf, float* __restrict__ Cb)
{
    int dir = blockIdx.z;
    const float* B = dir ? Wb : Wf;
    const float* bias = dir ? bb : bf;
    float* C = dir ? Cb : Cf;
    const float* At = A + (size_t)blockIdx.y * 128 * HID;
    const float* Bt = B + (size_t)blockIdx.x * 128 * HID;
    const float* bias_t = bias + blockIdx.x * 128;
    float* Ct = C + (size_t)blockIdx.y * 128 * (4 * HL) + blockIdx.x * 128;
    mma_nt_body_1x(At, HID, Bt, HID, bias_t, Ct, 4 * HL, HID);
}

// Projection GEMM (1x tf32): out[8192,256] = ys[8192,1024] @ Wp[256,1024]^T
__global__ void __launch_bounds__(256, 2) mma_proj_kernel(
    const float* __restrict__ A, const float* __restrict__ B,
    const float* __restrict__ bias, float* __restrict__ C)
{
    const float* At = A + (size_t)blockIdx.y * 128 * (2 * HL);
    const float* Bt = B + (size_t)blockIdx.x * 128 * (2 * HL);
    const float* bias_t = bias + blockIdx.x * 128;
    float* Ct = C + (size_t)blockIdx.y * 128 * EOUT + blockIdx.x * 128;
    mma_nt_body_1x(At, 2 * HL, Bt, 2 * HL, bias_t, Ct, EOUT, 2 * HL);
}

// ---------------------------------------------------------------------------
// W transpose: Wt[l][n][k] = W[l][k][n]
// ---------------------------------------------------------------------------
__global__ void __launch_bounds__(256) transpose_w_kernel(
    const float* __restrict__ W, float* __restrict__ Wt)
{
    __shared__ float tile[32][33];
    int l = blockIdx.z;
    int k0 = blockIdx.y * 32, n0 = blockIdx.x * 32;
    const float* Win = W + (size_t)l * HID * HID;
    float* Wout = Wt + (size_t)l * HID * HID;
    int x = threadIdx.x & 31, y = (threadIdx.x >> 5) * 4;
#pragma unroll
    for (int i = 0; i < 4; i++)
        tile[y + i][x] = Win[(size_t)(k0 + y + i) * HID + n0 + x];
    __syncthreads();
#pragma unroll
    for (int i = 0; i < 4; i++)
        Wout[(size_t)(n0 + y + i) * HID + k0 + x] = tile[x][y + i];
}

// ---------------------------------------------------------------------------
// Language-id normalization (dtype-robust)
// ---------------------------------------------------------------------------
__global__ void lang_normalize_kernel(const int* __restrict__ raw)
{
    __shared__ int first[32];
    int t = threadIdx.x;
    first[t] = raw[t];
    __syncwarp();
    bool odd_zero = true;
#pragma unroll
    for (int i = 1; i < 32; i += 2) odd_zero &= (first[i] == 0);
    int v = odd_zero ? raw[2 * t] : first[t];
    v = v < 0 ? 0 : (v >= NLANG ? NLANG - 1 : v);
    g_lang[t] = v;
}

// ---------------------------------------------------------------------------
// LayerNorm (biased var) + ReLU, in place
// ---------------------------------------------------------------------------
__global__ void __launch_bounds__(256) ln_relu_kernel(
    float* __restrict__ h, const float* __restrict__ ln_g_all,
    const float* __restrict__ ln_b_all)
{
    int row = blockIdx.x;
    int b = row >> 8;
    int l = g_lang[b];
    float4* x = (float4*)(h + (size_t)row * HID);
    float4 v = x[threadIdx.x];
    float s = v.x + v.y + v.z + v.w;
    float ss = v.x * v.x + v.y * v.y + v.z * v.z + v.w * v.w;
#pragma unroll
    for (int o = 16; o; o >>= 1) {
        s += __shfl_xor_sync(0xffffffffu, s, o);
        ss += __shfl_xor_sync(0xffffffffu, ss, o);
    }
    __shared__ float rs[8], rss[8];
    __shared__ float smean, sinv;
    int w = threadIdx.x >> 5;
    if ((threadIdx.x & 31) == 0) { rs[w] = s; rss[w] = ss; }
    __syncthreads();
    if (threadIdx.x == 0) {
        float S = 0.f, SS = 0.f;
#pragma unroll
        for (int i = 0; i < 8; i++) { S += rs[i]; SS += rss[i]; }
        float mean = S * (1.f / 1024.f);
        float var = SS * (1.f / 1024.f) - mean * mean;
        smean = mean;
        sinv = rsqrtf(var + 1e-5f);
    }
    __syncthreads();
    float mean = smean, inv = sinv;
    float4 g4 = *((const float4*)(ln_g_all + (size_t)l * HID) + threadIdx.x);
    float4 b4 = *((const float4*)(ln_b_all + (size_t)l * HID) + threadIdx.x);
    v.x = fmaxf((v.x - mean) * inv * g4.x + b4.x, 0.f);
    v.y = fmaxf((v.y - mean) * inv * g4.y + b4.y, 0.f);
    v.z = fmaxf((v.z - mean) * inv * g4.z + b4.z, 0.f);
    v.w = fmaxf((v.w - mean) * inv * g4.w + b4.w, 0.f);
    x[threadIdx.x] = v;
}

// ---------------------------------------------------------------------------
// Persistent BiLSTM — register-resident Whh + broadcast h + warp-local staging.
// Grid barrier uses release-atomic arrive + acquire-load poll (no MEMBAR.GPU).
// ---------------------------------------------------------------------------
#define LSTM_HS_FLOATS (512 * 32)                 // 64 KB
#define LSTM_GS_FLOATS (8 * 32 * 36)              // 36 KB
#define LSTM_SMEM_BYTES ((LSTM_HS_FLOATS + LSTM_GS_FLOATS) * 4)

__device__ __forceinline__ float sigf(float x) { return 1.f / (1.f + expf(-x)); }

__global__ void __launch_bounds__(256, 1) lstm_kernel(
    const float* __restrict__ gates_f, const float* __restrict__ gates_b,
    const float* __restrict__ Whh_fw, const float* __restrict__ Whh_bw,
    const int* __restrict__ mask, float* __restrict__ ys)
{
    extern __shared__ float sm[];
    float* hs = sm;                                // [512][32]
    float* gsm = sm + LSTM_HS_FLOATS;              // [8][32][36]

    int tid = threadIdx.x;
    int dir = blockIdx.y;
    int u0 = blockIdx.x * 8;
    const float* Whh = dir ? Whh_bw : Whh_fw;
    const float* G = dir ? gates_b : gates_f;

    int lane = tid & 31, wp = tid >> 5;
    int grow = (lane >> 3) * HL + u0 + (lane & 7);
    int ks = wp * 64;

    float w_reg[64];
    {
        const float4* wsrc = (const float4*)(Whh + (size_t)grow * HL + ks);
#pragma unroll
        for (int j = 0; j < 16; j++) {
            float4 v = wsrc[j];
            w_reg[4 * j + 0] = v.x; w_reg[4 * j + 1] = v.y;
            w_reg[4 * j + 2] = v.z; w_reg[4 * j + 3] = v.w;
        }
    }

    int cu = tid >> 5;
    int cb = tid & 31;
    float c = 0.f;

    float* grow_out = gsm + (wp * 32 + lane) * 36;
    float4* hdst_seg = (float4*)(hs + ks * 32);

    for (int t = 0; t < SEQ; ++t) {
        int s = dir ? (SEQ - 1 - t) : t;
        int pp = t & 1;

        size_t gbase = ((size_t)(cb * SEQ + s)) * (4 * HL) + u0 + cu;
        float gi = G[gbase];
        float gf = G[gbase + 512];
        float gg = G[gbase + 1024];
        float go = G[gbase + 1536];
        int m = mask[cb * SEQ + s];

        {
            const float4* hsrc = (const float4*)(&g_h[dir][pp][0][0]) + ks * 8;
#pragma unroll
            for (int i = 0; i < 16; ++i)
                hdst_seg[lane + 32 * i] = __ldcg(hsrc + lane + 32 * i);
        }
        __syncwarp();

        ull acc[16];
#pragma unroll
        for (int j = 0; j < 16; j++) acc[j] = 0ull;
#pragma unroll
        for (int k = 0; k < 64; ++k) {
            uint32_t wb = __float_as_uint(w_reg[k]);
            ull w2;
            asm("mov.b64 %0, {%1, %1};" : "=l"(w2) : "r"(wb));
            const ulonglong2* hp = (const ulonglong2*)(hs + (ks + k) * 32);
#pragma unroll
            for (int j = 0; j < 8; ++j) {
                ulonglong2 h2 = hp[j];
                ffma2(acc[2 * j], w2, h2.x);
                ffma2(acc[2 * j + 1], w2, h2.y);
            }
        }
#pragma unroll
        for (int j = 0; j < 8; ++j) {
            ulonglong2 o;
            o.x = acc[2 * j]; o.y = acc[2 * j + 1];
            *(ulonglong2*)(grow_out + 4 * j) = o;
        }
        __syncthreads();

        {
            float ii = gi, ff = gf, g2 = gg, oo = go;
#pragma unroll
            for (int w = 0; w < 8; ++w) {
                const float* base = gsm + w * (32 * 36) + cb;
                ii += base[(0 * 8 + cu) * 36];
                ff += base[(1 * 8 + cu) * 36];
                g2 += base[(2 * 8 + cu) * 36];
                oo += base[(3 * 8 + cu) * 36];
            }
            float cn = sigf(ff) * c + sigf(ii) * tanhf(g2);
            float hn = sigf(oo) * tanhf(cn);
            float hold = hs[(u0 + cu) * 32 + cb];
            float hw = m ? hn : hold;
            c = m ? cn : c;
            g_h[dir][1 - pp][u0 + cu][cb] = hw;
            ys[((size_t)(cb * SEQ + s)) * (2 * HL) + dir * HL + u0 + cu] = m ? hn : 0.f;
        }

        __syncthreads();
        if (tid == 0) {
            bar_arrive(&g_bar[dir]);
            unsigned tgt = 64u * (unsigned)(t + 1);
            while (bar_poll(&g_bar[dir]) < tgt) { }
        }
        __syncthreads();
    }
}

// ---------------------------------------------------------------------------
// Launch
// ---------------------------------------------------------------------------
extern "C" void kernel_launch(void* const* d_in, const int* in_sizes, int n_in,
                              void* d_out, int out_size)
{
    const float* seq_out = (const float*)d_in[0];
    const int* attn_mask = (const int*)d_in[1];
    const int* lang_raw = (const int*)d_in[2];
    const float* W1 = (const float*)d_in[3];
    const float* b1 = (const float*)d_in[4];
    const float* ln_g = (const float*)d_in[5];
    const float* ln_b = (const float*)d_in[6];
    const float* W2 = (const float*)d_in[7];
    const float* b2 = (const float*)d_in[8];
    const float* Wih_f = (const float*)d_in[9];
    const float* Whh_f = (const float*)d_in[10];
    const float* b_f = (const float*)d_in[11];
    const float* Wih_b = (const float*)d_in[12];
    const float* Whh_b = (const float*)d_in[13];
    const float* b_b = (const float*)d_in[14];
    const float* Wp = (const float*)d_in[15];
    const float* bp = (const float*)d_in[16];
    float* out = (float*)d_out;

    float* h1;       cudaGetSymbolAddress((void**)&h1, g_h1);
    float* adapted;  cudaGetSymbolAddress((void**)&adapted, g_adapted);
    float* gates_f;  cudaGetSymbolAddress((void**)&gates_f, g_gates_f);
    float* gates_b;  cudaGetSymbolAddress((void**)&gates_b, g_gates_b);
    float* ys;       cudaGetSymbolAddress((void**)&ys, g_ys);
    float* Wt1;      cudaGetSymbolAddress((void**)&Wt1, g_Wt1);
    float* Wt2;      cudaGetSymbolAddress((void**)&Wt2, g_Wt2);
    void* h_ptr;     cudaGetSymbolAddress(&h_ptr, g_h);
    void* bar_ptr;   cudaGetSymbolAddress(&bar_ptr, g_bar);

    cudaFuncSetAttribute(lstm_kernel,
                         cudaFuncAttributeMaxDynamicSharedMemorySize,
                         LSTM_SMEM_BYTES);

    cudaMemsetAsync(h_ptr, 0, sizeof(float) * 2 * 2 * HL * BATCH);
    cudaMemsetAsync(bar_ptr, 0, sizeof(unsigned) * 2);

    // 0) normalize language ids + transpose adapter weights
    lang_normalize_kernel<<<1, 32>>>(lang_raw);
    transpose_w_kernel<<<dim3(32, 32, NLANG), 256>>>(W1, Wt1);
    transpose_w_kernel<<<dim3(32, 32, NLANG), 256>>>(W2, Wt2);
    // 1) adapter GEMM1 (1x tf32, double-buffered)
    mma_adapter_kernel<<<dim3(HID / 128, SEQ / 128, BATCH), 256>>>(
        seq_out, Wt1, b1, h1);
    // 2) LN + ReLU
    ln_relu_kernel<<<BATCH * SEQ, 256>>>(h1, ln_g, ln_b);
    // 3) adapter GEMM2 (1x tf32, double-buffered)
    mma_adapter_kernel<<<dim3(HID / 128, SEQ / 128, BATCH), 256>>>(
        h1, Wt2, b2, adapted);
    // 4) input-gate precompute, BOTH directions in one launch
    mma_gates_kernel<<<dim3(4 * HL / 128, BATCH * SEQ / 128, 2), 256>>>(
        adapted, Wih_f, Wih_b, b_f, b_b, gates_f, gates_b);
    // 5) persistent BiLSTM
    lstm_kernel<<<dim3(64, 2), 256, LSTM_SMEM_BYTES>>>(
        gates_f, gates_b, Whh_f, Whh_b, attn_mask, ys);
    // 6) projection (1x tf32 mma)
    mma_proj_kernel<<<dim3(EOUT / 128, BATCH * SEQ / 128), 256>>>(
        ys, Wp, bp, out);
}

// round 17
// speedup vs baseline: 2.0907x; 1.3843x over previous
#include <cuda_runtime.h>
#include <cuda_bf16.h>
#include <cstdint>

// Problem constants
#define BATCH 32
#define SEQ   256
#define HID   1024
#define HL    512
#define EOUT  256
#define NLANG 5

typedef unsigned long long ull;

// ---------------------------------------------------------------------------
// Scratch (device globals — no allocation allowed)
// ---------------------------------------------------------------------------
__device__ float g_h1[BATCH * SEQ * HID];
__device__ float g_adapted[BATCH * SEQ * HID];
__device__ float g_gates_f[BATCH * SEQ * 4 * HL];
__device__ float g_gates_b[BATCH * SEQ * 4 * HL];
__device__ float g_ys[BATCH * SEQ * 2 * HL];
__device__ float g_h[2][2][HL][BATCH];     // dir, pingpong, UNIT, BATCH
__device__ unsigned g_bar[2];
__device__ int   g_lang[BATCH];
__device__ float g_Wt1[NLANG * HID * HID];   // W1^T: [l][n][k]
__device__ float g_Wt2[NLANG * HID * HID];   // W2^T

// ---------------------------------------------------------------------------
// tf32 + mma.sync helpers
// ---------------------------------------------------------------------------
__device__ __forceinline__ uint32_t tf32_cvt(float x)
{
    uint32_t h;
    asm("cvt.rna.tf32.f32 %0, %1;" : "=r"(h) : "f"(x));
    return h;
}

__device__ __forceinline__ void mma8(float* d, const uint32_t* a, const uint32_t* b)
{
    asm volatile(
        "mma.sync.aligned.m16n8k8.row.col.f32.tf32.tf32.f32 "
        "{%0,%1,%2,%3}, {%4,%5,%6,%7}, {%8,%9}, {%0,%1,%2,%3};"
        : "+f"(d[0]), "+f"(d[1]), "+f"(d[2]), "+f"(d[3])
        : "r"(a[0]), "r"(a[1]), "r"(a[2]), "r"(a[3]), "r"(b[0]), "r"(b[1]));
}

// release/acquire barrier primitives (no full MEMBAR)
__device__ __forceinline__ void bar_arrive(unsigned* p)
{
    unsigned old;
    asm volatile("atom.add.release.gpu.global.u32 %0, [%1], 1;"
                 : "=r"(old) : "l"(p) : "memory");
}
__device__ __forceinline__ unsigned bar_poll(const unsigned* p)
{
    unsigned v;
    asm volatile("ld.acquire.gpu.global.u32 %0, [%1];" : "=r"(v) : "l"(p) : "memory");
    return v;
}

#define BKC 16
#define MM_PAD1 136

// ---------------------------------------------------------------------------
// Single-pass tf32 NT GEMM body, DOUBLE-BUFFERED (one sync per chunk):
// C[128,128] = A[128,K] @ B[128,K]^T + bias
// 256 threads, 8 warps (4M x 2N), warp tile 32x64.
// ---------------------------------------------------------------------------
__device__ __forceinline__ void mma_nt_body_1x(
    const float* __restrict__ At, int lda,
    const float* __restrict__ Bt, int ldb,
    const float* __restrict__ bias_t,
    float* __restrict__ Ct, int ldc,
    int K)
{
    __shared__ uint32_t As1[2][BKC][MM_PAD1];
    __shared__ uint32_t Bs1[2][BKC][MM_PAD1];

    int tid = threadIdx.x;
    int lane = tid & 31, wid = tid >> 5;
    int warpM = wid & 3, warpN = wid >> 2;
    int m0 = warpM * 32, n0w = warpN * 64;
    int g = lane >> 2, t4 = lane & 3;

    int r = tid >> 1, cq = (tid & 1) * 8;
    const float* Arow = At + (size_t)r * lda + cq;
    const float* Brow = Bt + (size_t)r * ldb + cq;

    float acc[2][8][4];
#pragma unroll
    for (int mi = 0; mi < 2; mi++)
#pragma unroll
        for (int ni = 0; ni < 8; ni++)
#pragma unroll
            for (int q = 0; q < 4; q++) acc[mi][ni][q] = 0.f;

    int nch = K >> 4;
    float4 pa0, pa1, pb0, pb1;

    pa0 = *(const float4*)(Arow);
    pa1 = *(const float4*)(Arow + 4);
    pb0 = *(const float4*)(Brow);
    pb1 = *(const float4*)(Brow + 4);
    {
        As1[0][cq + 0][r] = tf32_cvt(pa0.x); As1[0][cq + 1][r] = tf32_cvt(pa0.y);
        As1[0][cq + 2][r] = tf32_cvt(pa0.z); As1[0][cq + 3][r] = tf32_cvt(pa0.w);
        As1[0][cq + 4][r] = tf32_cvt(pa1.x); As1[0][cq + 5][r] = tf32_cvt(pa1.y);
        As1[0][cq + 6][r] = tf32_cvt(pa1.z); As1[0][cq + 7][r] = tf32_cvt(pa1.w);
        Bs1[0][cq + 0][r] = tf32_cvt(pb0.x); Bs1[0][cq + 1][r] = tf32_cvt(pb0.y);
        Bs1[0][cq + 2][r] = tf32_cvt(pb0.z); Bs1[0][cq + 3][r] = tf32_cvt(pb0.w);
        Bs1[0][cq + 4][r] = tf32_cvt(pb1.x); Bs1[0][cq + 5][r] = tf32_cvt(pb1.y);
        Bs1[0][cq + 6][r] = tf32_cvt(pb1.z); Bs1[0][cq + 7][r] = tf32_cvt(pb1.w);
    }
    if (nch > 1) {
        pa0 = *(const float4*)(Arow + BKC);
        pa1 = *(const float4*)(Arow + BKC + 4);
        pb0 = *(const float4*)(Brow + BKC);
        pb1 = *(const float4*)(Brow + BKC + 4);
    }
    __syncthreads();

    for (int c = 0; c < nch; ++c) {
        int buf = c & 1;
        if (c + 1 < nch) {
            int ob = buf ^ 1;
            As1[ob][cq + 0][r] = tf32_cvt(pa0.x); As1[ob][cq + 1][r] = tf32_cvt(pa0.y);
            As1[ob][cq + 2][r] = tf32_cvt(pa0.z); As1[ob][cq + 3][r] = tf32_cvt(pa0.w);
            As1[ob][cq + 4][r] = tf32_cvt(pa1.x); As1[ob][cq + 5][r] = tf32_cvt(pa1.y);
            As1[ob][cq + 6][r] = tf32_cvt(pa1.z); As1[ob][cq + 7][r] = tf32_cvt(pa1.w);
            Bs1[ob][cq + 0][r] = tf32_cvt(pb0.x); Bs1[ob][cq + 1][r] = tf32_cvt(pb0.y);
            Bs1[ob][cq + 2][r] = tf32_cvt(pb0.z); Bs1[ob][cq + 3][r] = tf32_cvt(pb0.w);
            Bs1[ob][cq + 4][r] = tf32_cvt(pb1.x); Bs1[ob][cq + 5][r] = tf32_cvt(pb1.y);
            Bs1[ob][cq + 6][r] = tf32_cvt(pb1.z); Bs1[ob][cq + 7][r] = tf32_cvt(pb1.w);
        }
        if (c + 2 < nch) {
            int k0 = (c + 2) * BKC;
            pa0 = *(const float4*)(Arow + k0);
            pa1 = *(const float4*)(Arow + k0 + 4);
            pb0 = *(const float4*)(Brow + k0);
            pb1 = *(const float4*)(Brow + k0 + 4);
        }
#pragma unroll
        for (int ks = 0; ks < BKC; ks += 8) {
            uint32_t ah[2][4];
#pragma unroll
            for (int mi = 0; mi < 2; mi++) {
                int m = m0 + mi * 16;
                ah[mi][0] = As1[buf][ks + t4][m + g];
                ah[mi][1] = As1[buf][ks + t4][m + g + 8];
                ah[mi][2] = As1[buf][ks + t4 + 4][m + g];
                ah[mi][3] = As1[buf][ks + t4 + 4][m + g + 8];
            }
#pragma unroll
            for (int ni = 0; ni < 8; ni++) {
                int n = n0w + ni * 8 + g;
                uint32_t bh[2];
                bh[0] = Bs1[buf][ks + t4][n];
                bh[1] = Bs1[buf][ks + t4 + 4][n];
                mma8(acc[0][ni], ah[0], bh);
                mma8(acc[1][ni], ah[1], bh);
            }
        }
        __syncthreads();
    }

#pragma unroll
    for (int mi = 0; mi < 2; mi++) {
#pragma unroll
        for (int ni = 0; ni < 8; ni++) {
            int row0 = m0 + mi * 16 + g;
            int col = n0w + ni * 8 + 2 * t4;
            float2 b2 = *(const float2*)&bias_t[col];
            float2 o0 = {acc[mi][ni][0] + b2.x, acc[mi][ni][1] + b2.y};
            float2 o1 = {acc[mi][ni][2] + b2.x, acc[mi][ni][3] + b2.y};
            *(float2*)&Ct[(size_t)row0 * ldc + col] = o0;
            *(float2*)&Ct[(size_t)(row0 + 8) * ldc + col] = o1;
        }
    }
}

// Adapter GEMM (language-selected W): single-pass tf32
__global__ void __launch_bounds__(256, 2) mma_adapter_kernel(
    const float* __restrict__ Abase, const float* __restrict__ Wt,
    const float* __restrict__ ball, float* __restrict__ Cbase)
{
    int b = blockIdx.z;
    int l = g_lang[b];
    const float* At = Abase + (size_t)b * SEQ * HID + (size_t)blockIdx.y * 128 * HID;
    const float* Bt = Wt + (size_t)l * HID * HID + (size_t)blockIdx.x * 128 * HID;
    const float* bias_t = ball + (size_t)l * HID + blockIdx.x * 128;
    float* Ct = Cbase + (size_t)b * SEQ * HID + (size_t)blockIdx.y * 128 * HID
              + blockIdx.x * 128;
    mma_nt_body_1x(At, HID, Bt, HID, bias_t, Ct, HID, HID);
}

// Both gate GEMMs in ONE launch: blockIdx.z = direction
__global__ void __launch_bounds__(256, 2) mma_gates_kernel(
    const float* __restrict__ A,
    const float* __restrict__ Wf, const float* __restrict__ Wb,
    const float* __restrict__ bf, const float* __restrict__ bb,
    float* __restrict__ Cf, float* __restrict__ Cb)
{
    int dir = blockIdx.z;
    const float* B = dir ? Wb : Wf;
    const float* bias = dir ? bb : bf;
    float* C = dir ? Cb : Cf;
    const float* At = A + (size_t)blockIdx.y * 128 * HID;
    const float* Bt = B + (size_t)blockIdx.x * 128 * HID;
    const float* bias_t = bias + blockIdx.x * 128;
    float* Ct = C + (size_t)blockIdx.y * 128 * (4 * HL) + blockIdx.x * 128;
    mma_nt_body_1x(At, HID, Bt, HID, bias_t, Ct, 4 * HL, HID);
}

// Projection GEMM (1x tf32)
__global__ void __launch_bounds__(256, 2) mma_proj_kernel(
    const float* __restrict__ A, const float* __restrict__ B,
    const float* __restrict__ bias, float* __restrict__ C)
{
    const float* At = A + (size_t)blockIdx.y * 128 * (2 * HL);
    const float* Bt = B + (size_t)blockIdx.x * 128 * (2 * HL);
    const float* bias_t = bias + blockIdx.x * 128;
    float* Ct = C + (size_t)blockIdx.y * 128 * EOUT + blockIdx.x * 128;
    mma_nt_body_1x(At, 2 * HL, Bt, 2 * HL, bias_t, Ct, EOUT, 2 * HL);
}

// ---------------------------------------------------------------------------
// W transpose: Wt[l][n][k] = W[l][k][n]
// ---------------------------------------------------------------------------
__global__ void __launch_bounds__(256) transpose_w_kernel(
    const float* __restrict__ W, float* __restrict__ Wt)
{
    __shared__ float tile[32][33];
    int l = blockIdx.z;
    int k0 = blockIdx.y * 32, n0 = blockIdx.x * 32;
    const float* Win = W + (size_t)l * HID * HID;
    float* Wout = Wt + (size_t)l * HID * HID;
    int x = threadIdx.x & 31, y = (threadIdx.x >> 5) * 4;
#pragma unroll
    for (int i = 0; i < 4; i++)
        tile[y + i][x] = Win[(size_t)(k0 + y + i) * HID + n0 + x];
    __syncthreads();
#pragma unroll
    for (int i = 0; i < 4; i++)
        Wout[(size_t)(n0 + y + i) * HID + k0 + x] = tile[x][y + i];
}

// ---------------------------------------------------------------------------
// Language-id normalization (dtype-robust)
// ---------------------------------------------------------------------------
__global__ void lang_normalize_kernel(const int* __restrict__ raw)
{
    __shared__ int first[32];
    int t = threadIdx.x;
    first[t] = raw[t];
    __syncwarp();
    bool odd_zero = true;
#pragma unroll
    for (int i = 1; i < 32; i += 2) odd_zero &= (first[i] == 0);
    int v = odd_zero ? raw[2 * t] : first[t];
    v = v < 0 ? 0 : (v >= NLANG ? NLANG - 1 : v);
    g_lang[t] = v;
}

// ---------------------------------------------------------------------------
// LayerNorm (biased var) + ReLU, in place
// ---------------------------------------------------------------------------
__global__ void __launch_bounds__(256) ln_relu_kernel(
    float* __restrict__ h, const float* __restrict__ ln_g_all,
    const float* __restrict__ ln_b_all)
{
    int row = blockIdx.x;
    int b = row >> 8;
    int l = g_lang[b];
    float4* x = (float4*)(h + (size_t)row * HID);
    float4 v = x[threadIdx.x];
    float s = v.x + v.y + v.z + v.w;
    float ss = v.x * v.x + v.y * v.y + v.z * v.z + v.w * v.w;
#pragma unroll
    for (int o = 16; o; o >>= 1) {
        s += __shfl_xor_sync(0xffffffffu, s, o);
        ss += __shfl_xor_sync(0xffffffffu, ss, o);
    }
    __shared__ float rs[8], rss[8];
    __shared__ float smean, sinv;
    int w = threadIdx.x >> 5;
    if ((threadIdx.x & 31) == 0) { rs[w] = s; rss[w] = ss; }
    __syncthreads();
    if (threadIdx.x == 0) {
        float S = 0.f, SS = 0.f;
#pragma unroll
        for (int i = 0; i < 8; i++) { S += rs[i]; SS += rss[i]; }
        float mean = S * (1.f / 1024.f);
        float var = SS * (1.f / 1024.f) - mean * mean;
        smean = mean;
        sinv = rsqrtf(var + 1e-5f);
    }
    __syncthreads();
    float mean = smean, inv = sinv;
    float4 g4 = *((const float4*)(ln_g_all + (size_t)l * HID) + threadIdx.x);
    float4 b4 = *((const float4*)(ln_b_all + (size_t)l * HID) + threadIdx.x);
    v.x = fmaxf((v.x - mean) * inv * g4.x + b4.x, 0.f);
    v.y = fmaxf((v.y - mean) * inv * g4.y + b4.y, 0.f);
    v.z = fmaxf((v.z - mean) * inv * g4.z + b4.z, 0.f);
    v.w = fmaxf((v.w - mean) * inv * g4.w + b4.w, 0.f);
    x[threadIdx.x] = v;
}

// ---------------------------------------------------------------------------
// Persistent BiLSTM with TENSOR-CORE recurrence.
// Block: 8 units (32 gate-rows = M) x 32 batches (N) x K=512.
// Warp wp owns K-segment [64wp, 64wp+64): 8 k-steps, 2x4 mma tiles.
// Whh A-fragments preloaded in REGISTERS (64 regs) for all 256 steps.
// h staged per-warp in smem [unit][batch] with stride 40 (conflict-free
// B-fragment reads: bank = 8*t4+g covers all 32). Partials reduced via gsm.
// ---------------------------------------------------------------------------
#define HSTRIDE 40
#define LSTM_HS_FLOATS (512 * HSTRIDE)            // 80 KB
#define LSTM_GS_FLOATS (8 * 32 * 36)              // 36 KB
#define LSTM_SMEM_BYTES ((LSTM_HS_FLOATS + LSTM_GS_FLOATS) * 4)

__device__ __forceinline__ float sigf(float x) { return 1.f / (1.f + expf(-x)); }

__global__ void __launch_bounds__(256, 1) lstm_kernel(
    const float* __restrict__ gates_f, const float* __restrict__ gates_b,
    const float* __restrict__ Whh_fw, const float* __restrict__ Whh_bw,
    const int* __restrict__ mask, float* __restrict__ ys)
{
    extern __shared__ float sm[];
    float* hs = sm;                                // [512][HSTRIDE]
    float* gsm = sm + LSTM_HS_FLOATS;              // [8][32][36]

    int tid = threadIdx.x;
    int dir = blockIdx.y;
    int u0 = blockIdx.x * 8;
    const float* Whh = dir ? Whh_bw : Whh_fw;
    const float* G = dir ? gates_b : gates_f;

    int lane = tid & 31, wp = tid >> 5;
    int g = lane >> 2, t4 = lane & 3;
    int kb = wp * 64;

    // Preload Whh A-fragments (tf32) — resident for all 256 steps.
    // Tile row m (0..31): gate = m>>3, unit = m&7 -> global row gate*HL+u0+unit
    uint32_t afr[2][8][4];
#pragma unroll
    for (int mi = 0; mi < 2; mi++) {
        int mA = mi * 16 + g;
        int mB = mA + 8;
        int rA = (mA >> 3) * HL + u0 + (mA & 7);
        int rB = (mB >> 3) * HL + u0 + (mB & 7);
#pragma unroll
        for (int kst = 0; kst < 8; kst++) {
            int k0 = kb + kst * 8 + t4;
            afr[mi][kst][0] = tf32_cvt(Whh[(size_t)rA * HL + k0]);
            afr[mi][kst][1] = tf32_cvt(Whh[(size_t)rB * HL + k0]);
            afr[mi][kst][2] = tf32_cvt(Whh[(size_t)rA * HL + k0 + 4]);
            afr[mi][kst][3] = tf32_cvt(Whh[(size_t)rB * HL + k0 + 4]);
        }
    }

    int cu = tid >> 5;       // 0..7 (unit)
    int cb = tid & 31;       // 0..31 (batch)
    float c = 0.f;

    float* gseg = gsm + wp * (32 * 36);

    for (int t = 0; t < SEQ; ++t) {
        int s = dir ? (SEQ - 1 - t) : t;
        int pp = t & 1;

        // Prefetch input-gate contributions + mask
        size_t gbase = ((size_t)(cb * SEQ + s)) * (4 * HL) + u0 + cu;
        float gi = G[gbase];
        float gf = G[gbase + 512];
        float gg = G[gbase + 1024];
        float go = G[gbase + 1536];
        int m = mask[cb * SEQ + s];

        // Warp-local staging of h rows [kb, kb+64): 512 float4, 16 per lane
        {
            const float4* hsrc = (const float4*)(&g_h[dir][pp][0][0]) + kb * 8;
#pragma unroll
            for (int i = 0; i < 16; ++i) {
                int idx = lane + 32 * i;
                int row = idx >> 3, c4 = idx & 7;
                *(float4*)&hs[(kb + row) * HSTRIDE + c4 * 4] = __ldcg(hsrc + idx);
            }
        }
        __syncwarp();

        // Tensor-core recurrent GEMM: 2x4 tiles x 8 k-steps
        float acc[2][4][4];
#pragma unroll
        for (int mi = 0; mi < 2; mi++)
#pragma unroll
            for (int ni = 0; ni < 4; ni++)
#pragma unroll
                for (int q = 0; q < 4; q++) acc[mi][ni][q] = 0.f;
#pragma unroll
        for (int kst = 0; kst < 8; kst++) {
            int krow = (kb + kst * 8 + t4) * HSTRIDE;
#pragma unroll
            for (int ni = 0; ni < 4; ni++) {
                uint32_t bh[2];
                bh[0] = tf32_cvt(hs[krow + ni * 8 + g]);
                bh[1] = tf32_cvt(hs[krow + 4 * HSTRIDE + ni * 8 + g]);
                mma8(acc[0][ni], afr[0][kst], bh);
                mma8(acc[1][ni], afr[1][kst], bh);
            }
        }

        // Write partials to gsm[wp][row][col]
#pragma unroll
        for (int mi = 0; mi < 2; mi++) {
#pragma unroll
            for (int ni = 0; ni < 4; ni++) {
                int row = mi * 16 + g;
                int col = ni * 8 + 2 * t4;
                *(float2*)&gseg[row * 36 + col] =
                    make_float2(acc[mi][ni][0], acc[mi][ni][1]);
                *(float2*)&gseg[(row + 8) * 36 + col] =
                    make_float2(acc[mi][ni][2], acc[mi][ni][3]);
            }
        }
        __syncthreads();

        // Cell update: sum 8 k-segment partials per gate
        {
            float ii = gi, ff = gf, g2 = gg, oo = go;
#pragma unroll
            for (int w = 0; w < 8; ++w) {
                const float* base = gsm + w * (32 * 36) + cb;
                ii += base[(0 * 8 + cu) * 36];
                ff += base[(1 * 8 + cu) * 36];
                g2 += base[(2 * 8 + cu) * 36];
                oo += base[(3 * 8 + cu) * 36];
            }
            float cn = sigf(ff) * c + sigf(ii) * tanhf(g2);
            float hn = sigf(oo) * tanhf(cn);
            float hold = hs[(u0 + cu) * HSTRIDE + cb];
            float hw = m ? hn : hold;
            c = m ? cn : c;
            g_h[dir][1 - pp][u0 + cu][cb] = hw;
            ys[((size_t)(cb * SEQ + s)) * (2 * HL) + dir * HL + u0 + cu] = m ? hn : 0.f;
        }

        // Per-direction grid barrier (64 blocks)
        __syncthreads();
        if (tid == 0) {
            bar_arrive(&g_bar[dir]);
            unsigned tgt = 64u * (unsigned)(t + 1);
            while (bar_poll(&g_bar[dir]) < tgt) { }
        }
        __syncthreads();
    }
}

// ---------------------------------------------------------------------------
// Launch
// ---------------------------------------------------------------------------
extern "C" void kernel_launch(void* const* d_in, const int* in_sizes, int n_in,
                              void* d_out, int out_size)
{
    const float* seq_out = (const float*)d_in[0];
    const int* attn_mask = (const int*)d_in[1];
    const int* lang_raw = (const int*)d_in[2];
    const float* W1 = (const float*)d_in[3];
    const float* b1 = (const float*)d_in[4];
    const float* ln_g = (const float*)d_in[5];
    const float* ln_b = (const float*)d_in[6];
    const float* W2 = (const float*)d_in[7];
    const float* b2 = (const float*)d_in[8];
    const float* Wih_f = (const float*)d_in[9];
    const float* Whh_f = (const float*)d_in[10];
    const float* b_f = (const float*)d_in[11];
    const float* Wih_b = (const float*)d_in[12];
    const float* Whh_b = (const float*)d_in[13];
    const float* b_b = (const float*)d_in[14];
    const float* Wp = (const float*)d_in[15];
    const float* bp = (const float*)d_in[16];
    float* out = (float*)d_out;

    float* h1;       cudaGetSymbolAddress((void**)&h1, g_h1);
    float* adapted;  cudaGetSymbolAddress((void**)&adapted, g_adapted);
    float* gates_f;  cudaGetSymbolAddress((void**)&gates_f, g_gates_f);
    float* gates_b;  cudaGetSymbolAddress((void**)&gates_b, g_gates_b);
    float* ys;       cudaGetSymbolAddress((void**)&ys, g_ys);
    float* Wt1;      cudaGetSymbolAddress((void**)&Wt1, g_Wt1);
    float* Wt2;      cudaGetSymbolAddress((void**)&Wt2, g_Wt2);
    void* h_ptr;     cudaGetSymbolAddress(&h_ptr, g_h);
    void* bar_ptr;   cudaGetSymbolAddress(&bar_ptr, g_bar);

    cudaFuncSetAttribute(lstm_kernel,
                         cudaFuncAttributeMaxDynamicSharedMemorySize,
                         LSTM_SMEM_BYTES);

    cudaMemsetAsync(h_ptr, 0, sizeof(float) * 2 * 2 * HL * BATCH);
    cudaMemsetAsync(bar_ptr, 0, sizeof(unsigned) * 2);

    // 0) normalize language ids + transpose adapter weights
    lang_normalize_kernel<<<1, 32>>>(lang_raw);
    transpose_w_kernel<<<dim3(32, 32, NLANG), 256>>>(W1, Wt1);
    transpose_w_kernel<<<dim3(32, 32, NLANG), 256>>>(W2, Wt2);
    // 1) adapter GEMM1 (1x tf32)
    mma_adapter_kernel<<<dim3(HID / 128, SEQ / 128, BATCH), 256>>>(
        seq_out, Wt1, b1, h1);
    // 2) LN + ReLU
    ln_relu_kernel<<<BATCH * SEQ, 256>>>(h1, ln_g, ln_b);
    // 3) adapter GEMM2 (1x tf32)
    mma_adapter_kernel<<<dim3(HID / 128, SEQ / 128, BATCH), 256>>>(
        h1, Wt2, b2, adapted);
    // 4) input-gate precompute, BOTH directions in one launch
    mma_gates_kernel<<<dim3(4 * HL / 128, BATCH * SEQ / 128, 2), 256>>>(
        adapted, Wih_f, Wih_b, b_f, b_b, gates_f, gates_b);
    // 5) persistent BiLSTM (tensor-core recurrence)
    lstm_kernel<<<dim3(64, 2), 256, LSTM_SMEM_BYTES>>>(
        gates_f, gates_b, Whh_f, Whh_b, attn_mask, ys);
    // 6) projection (1x tf32 mma)
    mma_proj_kernel<<<dim3(EOUT / 128, BATCH * SEQ / 128), 256>>>(
        ys, Wp, bp, out);
}